// round 2
// baseline (speedup 1.0000x reference)
#include <cuda_runtime.h>

#define B_   32
#define S_   128
#define DAR  256
#define DENC 256
#define K_   12
#define N_   128
#define W_   116            // S - K
#define M_   (B_*W_)        // 3712
#define INV_E (1.0f/256.0f)

// scratch (allocation-free rule: __device__ globals)
__device__ __align__(16) float g_locC[M_ * K_ * DENC];   // layout [m][k][e]
__device__ __align__(16) float g_part[M_ * 24];          // per-site: 12 loss, 12 acc

// ---------------------------------------------------------------------------
// Kernel A: locC[m][k][e] = sum_a cF[b,w,a] * Wp[k,e,a]
// grid (58 m-tiles, 4 e-tiles, 12 k), 256 threads, 64x64 tile, BK=32, 4x4/thread
// ---------------------------------------------------------------------------
__global__ __launch_bounds__(256) void kA(const float* __restrict__ cF,
                                          const float* __restrict__ Wp) {
    __shared__ float As[64 * 32];
    __shared__ float Bs[64 * 32];

    const int mt = blockIdx.x, et = blockIdx.y, k = blockIdx.z;
    const int tid = threadIdx.x;
    const int mr = tid >> 4;        // 0..15 (4 m-rows each)
    const int er = tid & 15;        // 0..15 (4 e-cols each)
    const int fB = er & 7;          // swizzle key for Bs (== (row>>2)&7 for rows er*4+j)

    float acc[4][4] = {};

    for (int ac = 0; ac < 8; ac++) {
        const int a0 = ac * 32;
        // fill As (natural layout)
        #pragma unroll
        for (int r = 0; r < 2; r++) {
            int task = tid + r * 256;          // 512 float4 tasks
            int i = task >> 3, a4 = task & 7;
            int m = mt * 64 + i;
            int b = m / W_, w = m - b * W_;
            float4 v = *(const float4*)(cF + ((b * S_ + w) * DAR) + a0 + a4 * 4);
            *(float4*)(As + i * 32 + a4 * 4) = v;
        }
        // fill Bs with e-keyed XOR swizzle on the a dimension (float4 granularity)
        #pragma unroll
        for (int r = 0; r < 2; r++) {
            int task = tid + r * 256;
            int ei = task >> 3, a4 = task & 7;
            int e = et * 64 + ei;
            float4 v = *(const float4*)(Wp + ((k * DENC + e) * DAR) + a0 + a4 * 4);
            *(float4*)(Bs + ei * 32 + ((a4 ^ ((ei >> 2) & 7)) << 2)) = v;
        }
        __syncthreads();

        #pragma unroll
        for (int a = 0; a < 32; a++) {
            float rA[4], rB[4];
            #pragma unroll
            for (int i = 0; i < 4; i++) rA[i] = As[(mr * 4 + i) * 32 + a];
            const int colB = (((a >> 2) ^ fB) << 2) | (a & 3);
            #pragma unroll
            for (int j = 0; j < 4; j++) rB[j] = Bs[(er * 4 + j) * 32 + colB];
            #pragma unroll
            for (int i = 0; i < 4; i++)
                #pragma unroll
                for (int j = 0; j < 4; j++)
                    acc[i][j] = fmaf(rA[i], rB[j], acc[i][j]);
        }
        __syncthreads();
    }

    // write out: [m][k][e], float4 over e
    #pragma unroll
    for (int i = 0; i < 4; i++) {
        int m = mt * 64 + mr * 4 + i;
        float4 o = make_float4(acc[i][0], acc[i][1], acc[i][2], acc[i][3]);
        *(float4*)(g_locC + ((size_t)(m * K_ + k) << 8) + et * 64 + er * 4) = o;
    }
}

// ---------------------------------------------------------------------------
// Kernel B: per-(b,w) scores + logsumexp + acc
// 3712 CTAs, 256 threads. smem: neg rows (swizzled) + locC rows + partials
// ---------------------------------------------------------------------------
#define NEG_FLOATS   (140 * 256)          // rows 0..127 neg, 128..139 pos
#define LOCC_STRIDE  258
#define LOCC_FLOATS  (K_ * LOCC_STRIDE)   // 3096
#define SC_FLOATS    (4 * 12 * 144)       // 6912
#define SMEMB_FLOATS (NEG_FLOATS + LOCC_FLOATS + SC_FLOATS)
#define SMEMB_BYTES  (SMEMB_FLOATS * 4)   // 183392

__global__ __launch_bounds__(256) void kB(const float* __restrict__ enc,
                                          const void* __restrict__ extIdxRaw) {
    extern __shared__ float sm[];
    float* neg_s  = sm;                       // [n][swizzled e], stride 256
    float* locC_s = sm + NEG_FLOATS;          // [k][e], stride 258
    float* scores = sm + NEG_FLOATS + LOCC_FLOATS; // [part][12][144]

    const int blk = blockIdx.x;
    const int b = blk / W_, w = blk - b * W_;
    const int tid = threadIdx.x;
    const int wp = tid >> 5, lane = tid & 31;

    // dtype detection for extIdx: values < 4096, so int64 => every odd 32-bit
    // word of the buffer is zero. OR the first 16 odd words (uniform per block).
    const int* p32 = (const int*)extIdxRaw;
    int orv = 0;
    #pragma unroll
    for (int q = 0; q < 16; q++) orv |= p32[2 * q + 1];
    const bool is64 = (orv == 0);
    const long long* p64 = (const long long*)extIdxRaw;

    // stage 128 neg rows (gathered) + 12 pos rows, e-swizzled by (row>>3)&7
    for (int r = wp; r < 140; r += 8) {
        int row;
        if (r < 128) {
            size_t j = (size_t)(b * N_ + r) * W_ + w;
            int idx = is64 ? (int)p64[j] : p32[j];
            row = idx & (B_ * S_ - 1);            // safety mask (identity on valid data)
        } else {
            row = b * S_ + (r - 128) + 1 + w;     // pos for k = r-128
        }
        const float4* src = (const float4*)(enc + (size_t)row * DENC);
        const int f = (r >> 3) & 7;
        #pragma unroll
        for (int h = 0; h < 2; h++) {
            int e4 = lane + h * 32;
            float4 v = src[e4];
            *(float4*)(neg_s + r * 256 + ((e4 ^ f) << 2)) = v;
        }
    }
    // stage locC rows for this (b,w): [k][e], stride 258 (bank-spread for k-loads)
    for (int q = tid; q < 1536; q += 256) {
        int k = q >> 7, e2 = q & 127;
        float2 v = *(const float2*)(g_locC + (size_t)blk * 3072 + k * 256 + e2 * 2);
        *(float2*)(locC_s + k * LOCC_STRIDE + e2 * 2) = v;
    }
    __syncthreads();

    // main FMA: thread tile 4k x 8n, 4-way e-split; 54 tiles x 4 parts = 216 active
    const int part = tid >> 6;
    const int t = tid & 63;
    if (t < 54) {
        const int k0 = (t % 3) * 4;
        const int g = t / 3;          // 0..17
        const int n0 = g * 8;
        const int fN = g & 7;
        const int e0 = part * 64;
        float acc[4][8] = {};
        #pragma unroll 8
        for (int ee = 0; ee < 64; ee++) {
            const int e = e0 + ee;
            const int colOff = (((e >> 2) ^ fN) << 2) | (e & 3);
            float lc[4], ng[8];
            #pragma unroll
            for (int i = 0; i < 4; i++) lc[i] = locC_s[(k0 + i) * LOCC_STRIDE + e];
            #pragma unroll
            for (int j = 0; j < 8; j++) ng[j] = neg_s[(n0 + j) * 256 + colOff];
            #pragma unroll
            for (int i = 0; i < 4; i++)
                #pragma unroll
                for (int j = 0; j < 8; j++)
                    acc[i][j] = fmaf(lc[i], ng[j], acc[i][j]);
        }
        #pragma unroll
        for (int i = 0; i < 4; i++)
            #pragma unroll
            for (int j = 0; j < 8; j++)
                scores[(part * 12 + k0 + i) * 144 + n0 + j] = acc[i][j];
    }
    __syncthreads();

    // sum the 4 e-partials in place (result lives in part-0 region)
    for (int c = tid; c < 1728; c += 256) {
        float s = scores[c] + scores[1728 + c] + scores[2 * 1728 + c] + scores[3 * 1728 + c];
        scores[c] = s;
    }
    __syncthreads();

    // per-k logsumexp over [pos, 128 negs]; warp wp handles k = wp, wp+8
    for (int k = wp; k < K_; k += 8) {
        float v[4], mx = -1e30f;
        #pragma unroll
        for (int q = 0; q < 4; q++) {
            v[q] = scores[k * 144 + lane + q * 32] * INV_E;
            mx = fmaxf(mx, v[q]);
        }
        #pragma unroll
        for (int off = 16; off > 0; off >>= 1)
            mx = fmaxf(mx, __shfl_xor_sync(0xffffffffu, mx, off));
        const float pos = scores[k * 144 + 128 + k] * INV_E;
        const float mm = fmaxf(mx, pos);
        float se = 0.f;
        #pragma unroll
        for (int q = 0; q < 4; q++) se += __expf(v[q] - mm);
        #pragma unroll
        for (int off = 16; off > 0; off >>= 1)
            se += __shfl_xor_sync(0xffffffffu, se, off);
        if (lane == 0) {
            float total = se + __expf(pos - mm);
            float lse = mm + __logf(total);
            g_part[(size_t)blk * 24 + k]      = lse - pos;               // loss term
            g_part[(size_t)blk * 24 + 12 + k] = (pos >= mx) ? 1.f : 0.f; // argmax==0
        }
    }
}

// ---------------------------------------------------------------------------
// Kernel C: mean over 3712 sites -> out[0..11]=losses, out[12..23]=acc
// ---------------------------------------------------------------------------
__global__ __launch_bounds__(768) void kC(float* __restrict__ out) {
    const int j = threadIdx.x >> 5;   // 0..23
    const int lane = threadIdx.x & 31;
    float s = 0.f;
    for (int i = lane; i < M_; i += 32) s += g_part[(size_t)i * 24 + j];
    #pragma unroll
    for (int off = 16; off > 0; off >>= 1)
        s += __shfl_xor_sync(0xffffffffu, s, off);
    if (lane == 0) out[j] = s * (1.0f / (float)M_);
}

// ---------------------------------------------------------------------------
extern "C" void kernel_launch(void* const* d_in, const int* in_sizes, int n_in,
                              void* d_out, int out_size) {
    const float* cF  = (const float*)d_in[0];
    const float* enc = (const float*)d_in[1];
    const float* Wp  = (const float*)d_in[2];
    const void* eIdx = (const void*)d_in[3];
    float* out = (float*)d_out;

    static bool attrDone = false;
    if (!attrDone) {
        cudaFuncSetAttribute(kB, cudaFuncAttributeMaxDynamicSharedMemorySize, SMEMB_BYTES);
        attrDone = true;
    }

    dim3 gA(58, 4, 12);
    kA<<<gA, 256>>>(cF, Wp);
    kB<<<M_, 256, SMEMB_BYTES>>>(enc, eIdx);
    kC<<<1, 768>>>(out);
}

// round 4
// speedup vs baseline: 1.4299x; 1.4299x over previous
#include <cuda_runtime.h>

#define B_   32
#define S_   128
#define DAR  256
#define DENC 256
#define K_   12
#define N_   128
#define W_   116            // S - K
#define M_   (B_*W_)        // 3712
#define INV_E (1.0f/256.0f)

// scratch (allocation-free rule: __device__ globals)
__device__ __align__(16) float g_locC[M_ * K_ * DENC];     // [m][k][e]
__device__ __align__(16) float g_WpT[K_ * DAR * DENC];     // [k][a][e]
__device__ __align__(16) float g_part[M_ * 24];            // 12 loss + 12 acc per site

// ---------------- f32x2 helpers (packed dual-FMA, exact IEEE fp32) ----------
typedef unsigned long long ull;
__device__ __forceinline__ ull pack2(float lo, float hi) {
    ull r; asm("mov.b64 %0, {%1, %2};" : "=l"(r) : "f"(lo), "f"(hi)); return r;
}
__device__ __forceinline__ void unpack2(float& lo, float& hi, ull v) {
    asm("mov.b64 {%0, %1}, %2;" : "=f"(lo), "=f"(hi) : "l"(v));
}
__device__ __forceinline__ ull fma2(ull a, ull b, ull c) {
    ull d; asm("fma.rn.f32x2 %0, %1, %2, %3;" : "=l"(d) : "l"(a), "l"(b), "l"(c)); return d;
}
__device__ __forceinline__ ull add2(ull a, ull b) {
    ull d; asm("add.rn.f32x2 %0, %1, %2;" : "=l"(d) : "l"(a), "l"(b)); return d;
}
__device__ __forceinline__ void cp_async8(void* dst, const void* src) {
    unsigned d = (unsigned)__cvta_generic_to_shared(dst);
    asm volatile("cp.async.ca.shared.global [%0], [%1], 8;" :: "r"(d), "l"(src));
}
__device__ __forceinline__ void cp_commit() { asm volatile("cp.async.commit_group;"); }
__device__ __forceinline__ void cp_wait0()  { asm volatile("cp.async.wait_group 0;"); }

// ---------------------------------------------------------------------------
// kT: WpT[k][a][e] = Wp[k][e][a]   (32x32 smem tile transpose)
// ---------------------------------------------------------------------------
__global__ __launch_bounds__(256) void kT(const float* __restrict__ Wp) {
    __shared__ float t[32][33];
    const int k = blockIdx.z, e0 = blockIdx.y * 32, a0 = blockIdx.x * 32;
    const int tx = threadIdx.x & 31, ty = threadIdx.x >> 5;   // 32 x 8
    const float* src = Wp + ((size_t)k * DENC) * DAR;
    #pragma unroll
    for (int j = 0; j < 4; j++)
        t[ty + 8 * j][tx] = src[(size_t)(e0 + ty + 8 * j) * DAR + a0 + tx];
    __syncthreads();
    float* dst = g_WpT + ((size_t)k * DAR) * DENC;
    #pragma unroll
    for (int j = 0; j < 4; j++)
        dst[(size_t)(a0 + ty + 8 * j) * DENC + e0 + tx] = t[tx][ty + 8 * j];
}

// ---------------------------------------------------------------------------
// kA: locC[m][k][e] = sum_a cF[m][a] * WpT[k][a][e]
// tile 128m x 128e, BK=32, 256 thr, 8m x 8e per thread (FFMA2 over m-pairs)
// As[a][m]       stride 130 (EVEN -> 8B-aligned LDS.64), plain columns
// Bs[a][col(e)]  stride 130, col(e)=32*((e>>1)&3)+2*(e>>3)+(e&1)
// ---------------------------------------------------------------------------
#define AS_STRIDE 130
#define BS_STRIDE 130
#define STAGE_FLOATS (32*AS_STRIDE + 32*BS_STRIDE)    // 8320 (even)
#define KA_SMEM (2 * STAGE_FLOATS * 4)                // 66560 B

__global__ __launch_bounds__(256, 2) void kA(const float* __restrict__ cF) {
    extern __shared__ float sm[];
    const int mt = blockIdx.x, et = blockIdx.y, k = blockIdx.z;
    const int tid = threadIdx.x;
    const int mr = tid >> 4, er = tid & 15;

    const float* WpTk = g_WpT + (size_t)k * DAR * DENC;

    // staging task decode (A): 1024 float4 tasks; (B): 2048 8B tasks
    int Am[4], Aga[4];
    #pragma unroll
    for (int r = 0; r < 4; r++) {
        int task = tid + r * 256;
        int m = task >> 3, a4 = task & 7;
        Am[r] = m;
        int mg = mt * 128 + m;
        int b = mg / W_, w = mg - b * W_;
        Aga[r] = (b * S_ + w) * DAR + a4 * 4;
    }
    int Ba[8], Bco[8], Bge[8];
    #pragma unroll
    for (int r = 0; r < 8; r++) {
        int task = tid + r * 256;
        int a = task >> 6, e2 = task & 63;
        Ba[r] = a;
        Bco[r] = 32 * (e2 & 3) + 2 * (e2 >> 2);   // column for e-pair 2*e2 under colmap
        Bge[r] = et * 128 + e2 * 2;
    }

    ull acc2[4][8];
    #pragma unroll
    for (int p = 0; p < 4; p++)
        #pragma unroll
        for (int x = 0; x < 8; x++) acc2[p][x] = 0ull;

    float4 Areg[4];

    // prologue: stage 0
    {
        float* As = sm; float* Bs = sm + 32 * AS_STRIDE;
        #pragma unroll
        for (int r = 0; r < 4; r++) Areg[r] = *(const float4*)(cF + Aga[r] + 0);
        #pragma unroll
        for (int r = 0; r < 8; r++)
            cp_async8(Bs + Ba[r] * BS_STRIDE + Bco[r], WpTk + (size_t)(0 + Ba[r]) * DENC + Bge[r]);
        cp_commit();
        #pragma unroll
        for (int r = 0; r < 4; r++) {
            int a0 = ((tid + r * 256) & 7) * 4;
            float* dst = As + Am[r];
            dst[(a0 + 0) * AS_STRIDE] = Areg[r].x;
            dst[(a0 + 1) * AS_STRIDE] = Areg[r].y;
            dst[(a0 + 2) * AS_STRIDE] = Areg[r].z;
            dst[(a0 + 3) * AS_STRIDE] = Areg[r].w;
        }
    }

    for (int ac = 0; ac < 8; ac++) {
        cp_wait0();
        __syncthreads();
        float* As = sm + (ac & 1) * STAGE_FLOATS;
        float* Bs = As + 32 * AS_STRIDE;

        if (ac < 7) {   // issue next B stage (other buffer) + LDG next A
            const int anext = (ac + 1) * 32;
            float* Bs2 = sm + ((ac + 1) & 1) * STAGE_FLOATS + 32 * AS_STRIDE;
            #pragma unroll
            for (int r = 0; r < 4; r++) Areg[r] = *(const float4*)(cF + Aga[r] + anext);
            #pragma unroll
            for (int r = 0; r < 8; r++)
                cp_async8(Bs2 + Ba[r] * BS_STRIDE + Bco[r],
                          WpTk + (size_t)(anext + Ba[r]) * DENC + Bge[r]);
            cp_commit();
        }

        #pragma unroll
        for (int a = 0; a < 32; a++) {
            const float* Ar = As + a * AS_STRIDE + 2 * mr;   // even offsets -> aligned LDS.64
            const float* Br = Bs + a * BS_STRIDE + 2 * er;
            ull a2[4];
            #pragma unroll
            for (int p = 0; p < 4; p++) a2[p] = *(const ull*)(Ar + 32 * p);
            ull b2[8];
            #pragma unroll
            for (int j = 0; j < 4; j++) {
                float b0 = Br[32 * j + 0], b1 = Br[32 * j + 1];
                b2[2 * j]     = pack2(b0, b0);
                b2[2 * j + 1] = pack2(b1, b1);
            }
            #pragma unroll
            for (int p = 0; p < 4; p++)
                #pragma unroll
                for (int x = 0; x < 8; x++)
                    acc2[p][x] = fma2(a2[p], b2[x], acc2[p][x]);
        }

        if (ac < 7) {   // STS next A after compute (LDG latency covered)
            float* As2 = sm + ((ac + 1) & 1) * STAGE_FLOATS;
            #pragma unroll
            for (int r = 0; r < 4; r++) {
                int a0 = ((tid + r * 256) & 7) * 4;
                float* dst = As2 + Am[r];
                dst[(a0 + 0) * AS_STRIDE] = Areg[r].x;
                dst[(a0 + 1) * AS_STRIDE] = Areg[r].y;
                dst[(a0 + 2) * AS_STRIDE] = Areg[r].z;
                dst[(a0 + 3) * AS_STRIDE] = Areg[r].w;
            }
        }
    }

    // epilogue: acc2[p][x] holds m = mt*128 + 32p + 2mr (lo) / +1 (hi),
    //           e = et*128 + er*8 + x   (colmap inverse verified)
    #pragma unroll
    for (int p = 0; p < 4; p++) {
        float lo[8], hi[8];
        #pragma unroll
        for (int x = 0; x < 8; x++) unpack2(lo[x], hi[x], acc2[p][x]);
        const int mbase = mt * 128 + 32 * p + 2 * mr;
        float* d0 = g_locC + ((size_t)(mbase * K_ + k)) * 256 + et * 128 + er * 8;
        float* d1 = g_locC + ((size_t)((mbase + 1) * K_ + k)) * 256 + et * 128 + er * 8;
        *(float4*)(d0)     = make_float4(lo[0], lo[1], lo[2], lo[3]);
        *(float4*)(d0 + 4) = make_float4(lo[4], lo[5], lo[6], lo[7]);
        *(float4*)(d1)     = make_float4(hi[0], hi[1], hi[2], hi[3]);
        *(float4*)(d1 + 4) = make_float4(hi[4], hi[5], hi[6], hi[7]);
    }
}

// ---------------------------------------------------------------------------
// kB: per-site scores + logsumexp. 3712 CTAs x 288 threads.
// warp: lane = es*4 + ng  (8 e-splits x 4 row-groups); thread: 4 rows x 32 e.
// neg/pos rows streamed from L2 (read once); locC in smem [e][k^swz], stride 16.
// shfl-butterfly reduces the 8 e-splits; logsumexp as before.
// ---------------------------------------------------------------------------
__global__ __launch_bounds__(288, 2) void kB(const float* __restrict__ enc,
                                             const void* __restrict__ extIdxRaw) {
    __shared__ __align__(16) float locC_t[256 * 16];   // 16 KB (ull LDS -> need 8B align)
    __shared__ float scores[K_ * 144];                 // 6.9 KB

    const int blk = blockIdx.x;
    const int b = blk / W_, w = blk - b * W_;
    const int tid = threadIdx.x;
    const int wp = tid >> 5, lane = tid & 31;
    const int es = lane >> 2, ng = lane & 3;
    const int g = wp * 4 + ng;               // 0..35 -> rows g*4..g*4+3

    // extIdx dtype detection (int64 -> odd 32-bit words all zero)
    const int* p32 = (const int*)extIdxRaw;
    int orv = 0;
    #pragma unroll
    for (int q = 0; q < 16; q++) orv |= p32[2 * q + 1];
    const bool is64 = (orv == 0);
    const long long* p64 = (const long long*)extIdxRaw;

    // stage locC (12KB) transposed+swizzled: locC_t[e*16 + (k ^ (2*(e>>5)))]
    const float* lcg = g_locC + (size_t)blk * (K_ * 256);
    for (int q = tid; q < K_ * 256; q += 288) {
        int k = q >> 8, e = q & 255;
        locC_t[e * 16 + (k ^ ((e >> 5) << 1))] = lcg[q];
    }

    // row pointers (4 rows per thread, e-slice es*32)
    const float* rp[4];
    #pragma unroll
    for (int i = 0; i < 4; i++) {
        int r = g * 4 + i;
        int row;
        if (r < 128) {
            size_t j = (size_t)(b * N_ + r) * W_ + w;
            int idx = is64 ? (int)p64[j] : p32[j];
            row = idx & (B_ * S_ - 1);
        } else if (r < 140) {
            row = b * S_ + (r - 128) + 1 + w;
        } else row = 0;
        rp[i] = enc + (size_t)row * DENC + es * 32;
    }
    __syncthreads();

    ull acc[6][4];
    #pragma unroll
    for (int kp = 0; kp < 6; kp++)
        #pragma unroll
        for (int i = 0; i < 4; i++) acc[kp][i] = 0ull;

    const int sw = es << 1;
    float4 cur[4], nxt[4];
    #pragma unroll
    for (int i = 0; i < 4; i++) nxt[i] = *(const float4*)(rp[i]);

    #pragma unroll
    for (int ee4 = 0; ee4 < 8; ee4++) {
        #pragma unroll
        for (int i = 0; i < 4; i++) cur[i] = nxt[i];
        if (ee4 < 7) {
            #pragma unroll
            for (int i = 0; i < 4; i++) nxt[i] = *(const float4*)(rp[i] + (ee4 + 1) * 4);
        }
        #pragma unroll
        for (int d = 0; d < 4; d++) {
            const float* lcb = locC_t + (es * 32 + ee4 * 4 + d) * 16;
            ull lc[6];
            #pragma unroll
            for (int kp = 0; kp < 6; kp++) lc[kp] = *(const ull*)(lcb + ((2 * kp) ^ sw));
            #pragma unroll
            for (int i = 0; i < 4; i++) {
                float v = (d == 0) ? cur[i].x : (d == 1) ? cur[i].y : (d == 2) ? cur[i].z : cur[i].w;
                ull b2 = pack2(v, v);
                #pragma unroll
                for (int kp = 0; kp < 6; kp++)
                    acc[kp][i] = fma2(lc[kp], b2, acc[kp][i]);
            }
        }
    }

    // butterfly-reduce the 8 e-splits (lane bits 2,3,4)
    #pragma unroll
    for (int off = 4; off <= 16; off <<= 1)
        #pragma unroll
        for (int kp = 0; kp < 6; kp++)
            #pragma unroll
            for (int i = 0; i < 4; i++)
                acc[kp][i] = add2(acc[kp][i], __shfl_xor_sync(0xffffffffu, acc[kp][i], off));

    if (es == 0) {
        #pragma unroll
        for (int i = 0; i < 4; i++) {
            int r = g * 4 + i;
            if (r < 140) {
                #pragma unroll
                for (int kp = 0; kp < 6; kp++) {
                    float s0, s1; unpack2(s0, s1, acc[kp][i]);
                    scores[(2 * kp) * 144 + r]     = s0;
                    scores[(2 * kp + 1) * 144 + r] = s1;
                }
            }
        }
    }
    __syncthreads();

    // per-k logsumexp over [pos, 128 negs]; 9 warps cover 12 k
    for (int k = wp; k < K_; k += 9) {
        float v[4], mx = -1e30f;
        #pragma unroll
        for (int q = 0; q < 4; q++) {
            v[q] = scores[k * 144 + lane + q * 32] * INV_E;
            mx = fmaxf(mx, v[q]);
        }
        #pragma unroll
        for (int off = 16; off > 0; off >>= 1)
            mx = fmaxf(mx, __shfl_xor_sync(0xffffffffu, mx, off));
        const float pos = scores[k * 144 + 128 + k] * INV_E;
        const float mm = fmaxf(mx, pos);
        float se = 0.f;
        #pragma unroll
        for (int q = 0; q < 4; q++) se += __expf(v[q] - mm);
        #pragma unroll
        for (int off = 16; off > 0; off >>= 1)
            se += __shfl_xor_sync(0xffffffffu, se, off);
        if (lane == 0) {
            float lse = mm + __logf(se + __expf(pos - mm));
            g_part[(size_t)blk * 24 + k]      = lse - pos;
            g_part[(size_t)blk * 24 + 12 + k] = (pos >= mx) ? 1.f : 0.f;
        }
    }
}

// ---------------------------------------------------------------------------
// kC: mean over sites
// ---------------------------------------------------------------------------
__global__ __launch_bounds__(768) void kC(float* __restrict__ out) {
    const int j = threadIdx.x >> 5, lane = threadIdx.x & 31;
    float s = 0.f;
    for (int i = lane; i < M_; i += 32) s += g_part[(size_t)i * 24 + j];
    #pragma unroll
    for (int off = 16; off > 0; off >>= 1)
        s += __shfl_xor_sync(0xffffffffu, s, off);
    if (lane == 0) out[j] = s * (1.0f / (float)M_);
}

// ---------------------------------------------------------------------------
extern "C" void kernel_launch(void* const* d_in, const int* in_sizes, int n_in,
                              void* d_out, int out_size) {
    const float* cF  = (const float*)d_in[0];
    const float* enc = (const float*)d_in[1];
    const float* Wp  = (const float*)d_in[2];
    const void* eIdx = (const void*)d_in[3];
    float* out = (float*)d_out;

    static bool attrDone = false;
    if (!attrDone) {
        cudaFuncSetAttribute(kA, cudaFuncAttributeMaxDynamicSharedMemorySize, KA_SMEM);
        attrDone = true;
    }

    dim3 gT(8, 8, 12);
    kT<<<gT, 256>>>(Wp);
    dim3 gA(29, 2, 12);
    kA<<<gA, 256, KA_SMEM>>>(cF);
    kB<<<M_, 288>>>(enc, eIdx);
    kC<<<1, 768>>>(out);
}

// round 5
// speedup vs baseline: 1.4357x; 1.0041x over previous
#include <cuda_runtime.h>

#define B_   32
#define S_   128
#define DAR  256
#define DENC 256
#define K_   12
#define N_   128
#define W_   116            // S - K
#define M_   (B_*W_)        // 3712
#define INV_E (1.0f/256.0f)

// scratch (allocation-free rule: __device__ globals)
__device__ __align__(16) float g_locC[M_ * K_ * DENC];     // [m][k][e]
__device__ __align__(16) float g_WpT[K_ * DAR * DENC];     // [k][a][e]
__device__ __align__(16) float g_part[24 * M_];            // [j][site]; j<12 loss, j>=12 acc

// ---------------- f32x2 helpers (packed dual-FMA, exact IEEE fp32) ----------
typedef unsigned long long ull;
__device__ __forceinline__ ull pack2(float lo, float hi) {
    ull r; asm("mov.b64 %0, {%1, %2};" : "=l"(r) : "f"(lo), "f"(hi)); return r;
}
__device__ __forceinline__ void unpack2(float& lo, float& hi, ull v) {
    asm("mov.b64 {%0, %1}, %2;" : "=f"(lo), "=f"(hi) : "l"(v));
}
__device__ __forceinline__ ull fma2(ull a, ull b, ull c) {
    ull d; asm("fma.rn.f32x2 %0, %1, %2, %3;" : "=l"(d) : "l"(a), "l"(b), "l"(c)); return d;
}
__device__ __forceinline__ ull add2(ull a, ull b) {
    ull d; asm("add.rn.f32x2 %0, %1, %2;" : "=l"(d) : "l"(a), "l"(b)); return d;
}
__device__ __forceinline__ void cp_async8(void* dst, const void* src) {
    unsigned d = (unsigned)__cvta_generic_to_shared(dst);
    asm volatile("cp.async.ca.shared.global [%0], [%1], 8;" :: "r"(d), "l"(src));
}
__device__ __forceinline__ void cp_commit() { asm volatile("cp.async.commit_group;"); }
__device__ __forceinline__ void cp_wait0()  { asm volatile("cp.async.wait_group 0;"); }

// ---------------------------------------------------------------------------
// kT: WpT[k][a][e] = Wp[k][e][a]   (32x32 smem tile transpose)
// ---------------------------------------------------------------------------
__global__ __launch_bounds__(256) void kT(const float* __restrict__ Wp) {
    __shared__ float t[32][33];
    const int k = blockIdx.z, e0 = blockIdx.y * 32, a0 = blockIdx.x * 32;
    const int tx = threadIdx.x & 31, ty = threadIdx.x >> 5;   // 32 x 8
    const float* src = Wp + ((size_t)k * DENC) * DAR;
    #pragma unroll
    for (int j = 0; j < 4; j++)
        t[ty + 8 * j][tx] = src[(size_t)(e0 + ty + 8 * j) * DAR + a0 + tx];
    __syncthreads();
    float* dst = g_WpT + ((size_t)k * DAR) * DENC;
    #pragma unroll
    for (int j = 0; j < 4; j++)
        dst[(size_t)(a0 + ty + 8 * j) * DENC + e0 + tx] = t[tx][ty + 8 * j];
}

// ---------------------------------------------------------------------------
// kA: locC[m][k][e] = sum_a cF[m][a] * WpT[k][a][e]
// tile 128m x 128e, BK=32, 256 thr, 8m x 8e per thread.
// acc packed over e-pairs: acc2[i][x2] holds (e=8er+2x2, +1), i = m offset 0..7.
// As[a][m], Bs[a][e], both stride 132 (528B: 16B-aligned rows, LDS.128 legal).
// B per a-step: 2 LDS.128 -> 4 natural e-pairs. A: 2 LDS.128 -> 8 dup-packs.
// ---------------------------------------------------------------------------
#define TSTRIDE 132
#define STAGE_FLOATS (64 * TSTRIDE)                  // A(32 rows)+B(32 rows) = 8448
#define KA_SMEM (2 * STAGE_FLOATS * 4)               // 67584 B

__global__ __launch_bounds__(256, 2) void kA(const float* __restrict__ cF) {
    extern __shared__ float sm[];
    const int mt = blockIdx.x, et = blockIdx.y, k = blockIdx.z;
    const int tid = threadIdx.x;
    const int mr = tid >> 4, er = tid & 15;

    const float* WpTk = g_WpT + (size_t)k * DAR * DENC;

    // staging tasks: A = 1024 float4 (m,a4), 4/thread; B = 2048 8B (a,e2), 8/thread
    int Am[4], Aga[4];
    #pragma unroll
    for (int r = 0; r < 4; r++) {
        int task = tid + r * 256;
        int m = task >> 3, a4 = task & 7;
        Am[r] = m;
        int mg = mt * 128 + m;
        int b = mg / W_, w = mg - b * W_;
        Aga[r] = (b * S_ + w) * DAR + a4 * 4;
    }
    int Ba[8], Be2[8];
    #pragma unroll
    for (int r = 0; r < 8; r++) {
        int task = tid + r * 256;
        Ba[r] = task >> 6; Be2[r] = task & 63;
    }

    ull acc2[8][4];
    #pragma unroll
    for (int i = 0; i < 8; i++)
        #pragma unroll
        for (int x = 0; x < 4; x++) acc2[i][x] = 0ull;

    float4 Areg[4];

    // prologue: stage 0
    {
        float* As = sm; float* Bs = sm + 32 * TSTRIDE;
        #pragma unroll
        for (int r = 0; r < 4; r++) Areg[r] = *(const float4*)(cF + Aga[r]);
        #pragma unroll
        for (int r = 0; r < 8; r++)
            cp_async8(Bs + Ba[r] * TSTRIDE + 2 * Be2[r],
                      WpTk + (size_t)Ba[r] * DENC + et * 128 + 2 * Be2[r]);
        cp_commit();
        #pragma unroll
        for (int r = 0; r < 4; r++) {
            int a0 = ((tid + r * 256) & 7) * 4;
            float* dst = As + Am[r];
            dst[(a0 + 0) * TSTRIDE] = Areg[r].x;
            dst[(a0 + 1) * TSTRIDE] = Areg[r].y;
            dst[(a0 + 2) * TSTRIDE] = Areg[r].z;
            dst[(a0 + 3) * TSTRIDE] = Areg[r].w;
        }
    }

    for (int ac = 0; ac < 8; ac++) {
        cp_wait0();
        __syncthreads();
        float* As = sm + (ac & 1) * STAGE_FLOATS;
        float* Bs = As + 32 * TSTRIDE;

        if (ac < 7) {   // LDG next A + cp.async next B into other buffer
            const int anext = (ac + 1) * 32;
            float* Bs2 = sm + ((ac + 1) & 1) * STAGE_FLOATS + 32 * TSTRIDE;
            #pragma unroll
            for (int r = 0; r < 4; r++) Areg[r] = *(const float4*)(cF + Aga[r] + anext);
            #pragma unroll
            for (int r = 0; r < 8; r++)
                cp_async8(Bs2 + Ba[r] * TSTRIDE + 2 * Be2[r],
                          WpTk + (size_t)(anext + Ba[r]) * DENC + et * 128 + 2 * Be2[r]);
            cp_commit();
        }

        #pragma unroll
        for (int a = 0; a < 32; a++) {
            const float* Ar = As + a * TSTRIDE + 8 * mr;   // 16B-aligned
            const float* Br = Bs + a * TSTRIDE + 8 * er;   // 16B-aligned
            float4 aq0 = *(const float4*)(Ar);
            float4 aq1 = *(const float4*)(Ar + 4);
            float4 bq0 = *(const float4*)(Br);
            float4 bq1 = *(const float4*)(Br + 4);
            ull b2[4];
            b2[0] = pack2(bq0.x, bq0.y);
            b2[1] = pack2(bq0.z, bq0.w);
            b2[2] = pack2(bq1.x, bq1.y);
            b2[3] = pack2(bq1.z, bq1.w);
            ull aa[8];
            aa[0] = pack2(aq0.x, aq0.x); aa[1] = pack2(aq0.y, aq0.y);
            aa[2] = pack2(aq0.z, aq0.z); aa[3] = pack2(aq0.w, aq0.w);
            aa[4] = pack2(aq1.x, aq1.x); aa[5] = pack2(aq1.y, aq1.y);
            aa[6] = pack2(aq1.z, aq1.z); aa[7] = pack2(aq1.w, aq1.w);
            #pragma unroll
            for (int i = 0; i < 8; i++)
                #pragma unroll
                for (int x = 0; x < 4; x++)
                    acc2[i][x] = fma2(aa[i], b2[x], acc2[i][x]);
        }

        if (ac < 7) {   // STS next A after compute (LDG latency covered)
            float* As2 = sm + ((ac + 1) & 1) * STAGE_FLOATS;
            #pragma unroll
            for (int r = 0; r < 4; r++) {
                int a0 = ((tid + r * 256) & 7) * 4;
                float* dst = As2 + Am[r];
                dst[(a0 + 0) * TSTRIDE] = Areg[r].x;
                dst[(a0 + 1) * TSTRIDE] = Areg[r].y;
                dst[(a0 + 2) * TSTRIDE] = Areg[r].z;
                dst[(a0 + 3) * TSTRIDE] = Areg[r].w;
            }
        }
    }

    // epilogue: acc2[i][x2] -> m = mt*128 + 8mr + i, e = et*128 + 8er + 2x2(+1)
    #pragma unroll
    for (int i = 0; i < 8; i++) {
        float v[8];
        #pragma unroll
        for (int x = 0; x < 4; x++) unpack2(v[2 * x], v[2 * x + 1], acc2[i][x]);
        const int m = mt * 128 + mr * 8 + i;
        float* d = g_locC + ((size_t)(m * K_ + k)) * 256 + et * 128 + er * 8;
        *(float4*)(d)     = make_float4(v[0], v[1], v[2], v[3]);
        *(float4*)(d + 4) = make_float4(v[4], v[5], v[6], v[7]);
    }
}

// ---------------------------------------------------------------------------
// kB: per-site scores + logsumexp. 3712 CTAs x 288 threads.
// warp: lane = es*4 + ng (8 e-splits x 4 row-groups); thread: 4 rows x 32 e.
// rows streamed from L2; locC smem [e][k^swz] stride 16; shfl reduce e-splits.
// ---------------------------------------------------------------------------
__global__ __launch_bounds__(288, 2) void kB(const float* __restrict__ enc,
                                             const void* __restrict__ extIdxRaw) {
    __shared__ __align__(16) float locC_t[256 * 16];   // 16 KB
    __shared__ float scores[K_ * 144];                 // 6.9 KB

    const int blk = blockIdx.x;
    const int b = blk / W_, w = blk - b * W_;
    const int tid = threadIdx.x;
    const int wp = tid >> 5, lane = tid & 31;
    const int es = lane >> 2, ng = lane & 3;
    const int g = wp * 4 + ng;               // 0..35 -> rows g*4..g*4+3

    // extIdx dtype detection (int64 -> odd 32-bit words all zero)
    const int* p32 = (const int*)extIdxRaw;
    int orv = 0;
    #pragma unroll
    for (int q = 0; q < 16; q++) orv |= p32[2 * q + 1];
    const bool is64 = (orv == 0);
    const long long* p64 = (const long long*)extIdxRaw;

    // stage locC (12KB) transposed+swizzled: locC_t[e*16 + (k ^ (2*(e>>5)))]
    const float* lcg = g_locC + (size_t)blk * (K_ * 256);
    for (int q = tid; q < K_ * 256; q += 288) {
        int k = q >> 8, e = q & 255;
        locC_t[e * 16 + (k ^ ((e >> 5) << 1))] = lcg[q];
    }

    // row pointers (4 rows per thread, e-slice es*32)
    const float* rp[4];
    #pragma unroll
    for (int i = 0; i < 4; i++) {
        int r = g * 4 + i;
        int row;
        if (r < 128) {
            size_t j = (size_t)(b * N_ + r) * W_ + w;
            int idx = is64 ? (int)p64[j] : p32[j];
            row = idx & (B_ * S_ - 1);
        } else if (r < 140) {
            row = b * S_ + (r - 128) + 1 + w;
        } else row = 0;
        rp[i] = enc + (size_t)row * DENC + es * 32;
    }
    __syncthreads();

    ull acc[6][4];
    #pragma unroll
    for (int kp = 0; kp < 6; kp++)
        #pragma unroll
        for (int i = 0; i < 4; i++) acc[kp][i] = 0ull;

    const int sw = es << 1;
    float4 nxt[4];
    #pragma unroll
    for (int i = 0; i < 4; i++) nxt[i] = *(const float4*)(rp[i]);

    #pragma unroll
    for (int ee4 = 0; ee4 < 8; ee4++) {
        float4 cur[4];
        #pragma unroll
        for (int i = 0; i < 4; i++) cur[i] = nxt[i];
        if (ee4 < 7) {
            #pragma unroll
            for (int i = 0; i < 4; i++) nxt[i] = *(const float4*)(rp[i] + (ee4 + 1) * 4);
        }
        #pragma unroll
        for (int d = 0; d < 4; d++) {
            const float* lcb = locC_t + (es * 32 + ee4 * 4 + d) * 16;
            ull lc[6];
            #pragma unroll
            for (int kp = 0; kp < 6; kp++) lc[kp] = *(const ull*)(lcb + ((2 * kp) ^ sw));
            #pragma unroll
            for (int i = 0; i < 4; i++) {
                float v = (d == 0) ? cur[i].x : (d == 1) ? cur[i].y : (d == 2) ? cur[i].z : cur[i].w;
                ull b2 = pack2(v, v);
                #pragma unroll
                for (int kp = 0; kp < 6; kp++)
                    acc[kp][i] = fma2(lc[kp], b2, acc[kp][i]);
            }
        }
    }

    // butterfly-reduce the 8 e-splits (lane bits 2,3,4)
    #pragma unroll
    for (int off = 4; off <= 16; off <<= 1)
        #pragma unroll
        for (int kp = 0; kp < 6; kp++)
            #pragma unroll
            for (int i = 0; i < 4; i++)
                acc[kp][i] = add2(acc[kp][i], __shfl_xor_sync(0xffffffffu, acc[kp][i], off));

    if (es == 0) {
        #pragma unroll
        for (int i = 0; i < 4; i++) {
            int r = g * 4 + i;
            if (r < 140) {
                #pragma unroll
                for (int kp = 0; kp < 6; kp++) {
                    float s0, s1; unpack2(s0, s1, acc[kp][i]);
                    scores[(2 * kp) * 144 + r]     = s0;
                    scores[(2 * kp + 1) * 144 + r] = s1;
                }
            }
        }
    }
    __syncthreads();

    // per-k logsumexp over [pos, 128 negs]; 9 warps cover 12 k
    for (int k = wp; k < K_; k += 9) {
        float v[4], mx = -1e30f;
        #pragma unroll
        for (int q = 0; q < 4; q++) {
            v[q] = scores[k * 144 + lane + q * 32] * INV_E;
            mx = fmaxf(mx, v[q]);
        }
        #pragma unroll
        for (int off = 16; off > 0; off >>= 1)
            mx = fmaxf(mx, __shfl_xor_sync(0xffffffffu, mx, off));
        const float pos = scores[k * 144 + 128 + k] * INV_E;
        const float mm = fmaxf(mx, pos);
        float se = 0.f;
        #pragma unroll
        for (int q = 0; q < 4; q++) se += __expf(v[q] - mm);
        #pragma unroll
        for (int off = 16; off > 0; off >>= 1)
            se += __shfl_xor_sync(0xffffffffu, se, off);
        if (lane == 0) {
            float lse = mm + __logf(se + __expf(pos - mm));
            g_part[(size_t)k * M_ + blk]        = lse - pos;
            g_part[(size_t)(12 + k) * M_ + blk] = (pos >= mx) ? 1.f : 0.f;
        }
    }
}

// ---------------------------------------------------------------------------
// kC: 24 blocks, each sums a contiguous 3712-float segment
// ---------------------------------------------------------------------------
__global__ __launch_bounds__(256) void kC(float* __restrict__ out) {
    __shared__ float red[8];
    const int j = blockIdx.x;
    const int tid = threadIdx.x, lane = tid & 31, wp = tid >> 5;
    const float* src = g_part + (size_t)j * M_;
    float s = 0.f;
    for (int i = tid; i < M_; i += 256) s += src[i];
    #pragma unroll
    for (int off = 16; off > 0; off >>= 1)
        s += __shfl_xor_sync(0xffffffffu, s, off);
    if (lane == 0) red[wp] = s;
    __syncthreads();
    if (tid < 8) {
        float v = red[tid];
        #pragma unroll
        for (int off = 4; off > 0; off >>= 1)
            v += __shfl_xor_sync(0xffu, v, off);
        if (tid == 0) out[j] = v * (1.0f / (float)M_);
    }
}

// ---------------------------------------------------------------------------
extern "C" void kernel_launch(void* const* d_in, const int* in_sizes, int n_in,
                              void* d_out, int out_size) {
    const float* cF  = (const float*)d_in[0];
    const float* enc = (const float*)d_in[1];
    const float* Wp  = (const float*)d_in[2];
    const void* eIdx = (const void*)d_in[3];
    float* out = (float*)d_out;

    static bool attrDone = false;
    if (!attrDone) {
        cudaFuncSetAttribute(kA, cudaFuncAttributeMaxDynamicSharedMemorySize, KA_SMEM);
        attrDone = true;
    }

    dim3 gT(8, 8, 12);
    kT<<<gT, 256>>>(Wp);
    dim3 gA(29, 2, 12);
    kA<<<gA, 256, KA_SMEM>>>(cF);
    kB<<<M_, 288>>>(enc, eIdx);
    kC<<<24, 256>>>(out);
}

// round 6
// speedup vs baseline: 1.4478x; 1.0084x over previous
#include <cuda_runtime.h>

#define B_   32
#define S_   128
#define DAR  256
#define DENC 256
#define K_   12
#define N_   128
#define W_   116            // S - K
#define M_   (B_*W_)        // 3712
#define INV_E (1.0f/256.0f)

// scratch (allocation-free rule: __device__ globals)
__device__ __align__(16) float g_locC[M_ * K_ * DENC];     // [m][k][e]
__device__ __align__(16) float g_WpT[K_ * DAR * DENC];     // [k][a][e]
__device__ __align__(16) float g_part[24 * M_];            // [j][site]

// ---------------- f32x2 helpers (packed dual-FMA, exact IEEE fp32) ----------
typedef unsigned long long ull;
__device__ __forceinline__ ull pack2(float lo, float hi) {
    ull r; asm("mov.b64 %0, {%1, %2};" : "=l"(r) : "f"(lo), "f"(hi)); return r;
}
__device__ __forceinline__ void unpack2(float& lo, float& hi, ull v) {
    asm("mov.b64 {%0, %1}, %2;" : "=f"(lo), "=f"(hi) : "l"(v));
}
__device__ __forceinline__ ull fma2(ull a, ull b, ull c) {
    ull d; asm("fma.rn.f32x2 %0, %1, %2, %3;" : "=l"(d) : "l"(a), "l"(b), "l"(c)); return d;
}
__device__ __forceinline__ ull add2(ull a, ull b) {
    ull d; asm("add.rn.f32x2 %0, %1, %2;" : "=l"(d) : "l"(a), "l"(b)); return d;
}
__device__ __forceinline__ void cp_async8(void* dst, const void* src) {
    unsigned d = (unsigned)__cvta_generic_to_shared(dst);
    asm volatile("cp.async.ca.shared.global [%0], [%1], 8;" :: "r"(d), "l"(src));
}
__device__ __forceinline__ void cp_async16(void* dst, const void* src) {
    unsigned d = (unsigned)__cvta_generic_to_shared(dst);
    asm volatile("cp.async.cg.shared.global [%0], [%1], 16;" :: "r"(d), "l"(src));
}
__device__ __forceinline__ void cp_commit() { asm volatile("cp.async.commit_group;"); }
__device__ __forceinline__ void cp_wait0()  { asm volatile("cp.async.wait_group 0;"); }

// ---------------------------------------------------------------------------
// kT: WpT[k][a][e] = Wp[k][e][a]
// ---------------------------------------------------------------------------
__global__ __launch_bounds__(256) void kT(const float* __restrict__ Wp) {
    __shared__ float t[32][33];
    const int k = blockIdx.z, e0 = blockIdx.y * 32, a0 = blockIdx.x * 32;
    const int tx = threadIdx.x & 31, ty = threadIdx.x >> 5;
    const float* src = Wp + ((size_t)k * DENC) * DAR;
    #pragma unroll
    for (int j = 0; j < 4; j++)
        t[ty + 8 * j][tx] = src[(size_t)(e0 + ty + 8 * j) * DAR + a0 + tx];
    __syncthreads();
    float* dst = g_WpT + ((size_t)k * DAR) * DENC;
    #pragma unroll
    for (int j = 0; j < 4; j++)
        dst[(size_t)(a0 + ty + 8 * j) * DENC + e0 + tx] = t[tx][ty + 8 * j];
}

// ---------------------------------------------------------------------------
// kA: unchanged from round 5 (128x128 tile, FFMA2 over e-pairs, stride 132)
// ---------------------------------------------------------------------------
#define TSTRIDE 132
#define STAGE_FLOATS (64 * TSTRIDE)
#define KA_SMEM (2 * STAGE_FLOATS * 4)

__global__ __launch_bounds__(256, 2) void kA(const float* __restrict__ cF) {
    extern __shared__ float sm[];
    const int mt = blockIdx.x, et = blockIdx.y, k = blockIdx.z;
    const int tid = threadIdx.x;
    const int mr = tid >> 4, er = tid & 15;

    const float* WpTk = g_WpT + (size_t)k * DAR * DENC;

    int Am[4], Aga[4];
    #pragma unroll
    for (int r = 0; r < 4; r++) {
        int task = tid + r * 256;
        int m = task >> 3, a4 = task & 7;
        Am[r] = m;
        int mg = mt * 128 + m;
        int b = mg / W_, w = mg - b * W_;
        Aga[r] = (b * S_ + w) * DAR + a4 * 4;
    }
    int Ba[8], Be2[8];
    #pragma unroll
    for (int r = 0; r < 8; r++) {
        int task = tid + r * 256;
        Ba[r] = task >> 6; Be2[r] = task & 63;
    }

    ull acc2[8][4];
    #pragma unroll
    for (int i = 0; i < 8; i++)
        #pragma unroll
        for (int x = 0; x < 4; x++) acc2[i][x] = 0ull;

    float4 Areg[4];

    {
        float* As = sm; float* Bs = sm + 32 * TSTRIDE;
        #pragma unroll
        for (int r = 0; r < 4; r++) Areg[r] = *(const float4*)(cF + Aga[r]);
        #pragma unroll
        for (int r = 0; r < 8; r++)
            cp_async8(Bs + Ba[r] * TSTRIDE + 2 * Be2[r],
                      WpTk + (size_t)Ba[r] * DENC + et * 128 + 2 * Be2[r]);
        cp_commit();
        #pragma unroll
        for (int r = 0; r < 4; r++) {
            int a0 = ((tid + r * 256) & 7) * 4;
            float* dst = As + Am[r];
            dst[(a0 + 0) * TSTRIDE] = Areg[r].x;
            dst[(a0 + 1) * TSTRIDE] = Areg[r].y;
            dst[(a0 + 2) * TSTRIDE] = Areg[r].z;
            dst[(a0 + 3) * TSTRIDE] = Areg[r].w;
        }
    }

    for (int ac = 0; ac < 8; ac++) {
        cp_wait0();
        __syncthreads();
        float* As = sm + (ac & 1) * STAGE_FLOATS;
        float* Bs = As + 32 * TSTRIDE;

        if (ac < 7) {
            const int anext = (ac + 1) * 32;
            float* Bs2 = sm + ((ac + 1) & 1) * STAGE_FLOATS + 32 * TSTRIDE;
            #pragma unroll
            for (int r = 0; r < 4; r++) Areg[r] = *(const float4*)(cF + Aga[r] + anext);
            #pragma unroll
            for (int r = 0; r < 8; r++)
                cp_async8(Bs2 + Ba[r] * TSTRIDE + 2 * Be2[r],
                          WpTk + (size_t)(anext + Ba[r]) * DENC + et * 128 + 2 * Be2[r]);
            cp_commit();
        }

        #pragma unroll
        for (int a = 0; a < 32; a++) {
            const float* Ar = As + a * TSTRIDE + 8 * mr;
            const float* Br = Bs + a * TSTRIDE + 8 * er;
            float4 aq0 = *(const float4*)(Ar);
            float4 aq1 = *(const float4*)(Ar + 4);
            float4 bq0 = *(const float4*)(Br);
            float4 bq1 = *(const float4*)(Br + 4);
            ull b2[4];
            b2[0] = pack2(bq0.x, bq0.y);
            b2[1] = pack2(bq0.z, bq0.w);
            b2[2] = pack2(bq1.x, bq1.y);
            b2[3] = pack2(bq1.z, bq1.w);
            ull aa[8];
            aa[0] = pack2(aq0.x, aq0.x); aa[1] = pack2(aq0.y, aq0.y);
            aa[2] = pack2(aq0.z, aq0.z); aa[3] = pack2(aq0.w, aq0.w);
            aa[4] = pack2(aq1.x, aq1.x); aa[5] = pack2(aq1.y, aq1.y);
            aa[6] = pack2(aq1.z, aq1.z); aa[7] = pack2(aq1.w, aq1.w);
            #pragma unroll
            for (int i = 0; i < 8; i++)
                #pragma unroll
                for (int x = 0; x < 4; x++)
                    acc2[i][x] = fma2(aa[i], b2[x], acc2[i][x]);
        }

        if (ac < 7) {
            float* As2 = sm + ((ac + 1) & 1) * STAGE_FLOATS;
            #pragma unroll
            for (int r = 0; r < 4; r++) {
                int a0 = ((tid + r * 256) & 7) * 4;
                float* dst = As2 + Am[r];
                dst[(a0 + 0) * TSTRIDE] = Areg[r].x;
                dst[(a0 + 1) * TSTRIDE] = Areg[r].y;
                dst[(a0 + 2) * TSTRIDE] = Areg[r].z;
                dst[(a0 + 3) * TSTRIDE] = Areg[r].w;
            }
        }
    }

    #pragma unroll
    for (int i = 0; i < 8; i++) {
        float v[8];
        #pragma unroll
        for (int x = 0; x < 4; x++) unpack2(v[2 * x], v[2 * x + 1], acc2[i][x]);
        const int m = mt * 128 + mr * 8 + i;
        float* d = g_locC + ((size_t)(m * K_ + k)) * 256 + et * 128 + er * 8;
        *(float4*)(d)     = make_float4(v[0], v[1], v[2], v[3]);
        *(float4*)(d + 4) = make_float4(v[4], v[5], v[6], v[7]);
    }
}

// ---------------------------------------------------------------------------
// kB v3: per-site scores + logsumexp. 3712 CTAs x 288 threads, 1 CTA/SM.
// Warp wp owns rows [16wp, 16wp+16): gathers them with coalesced cp.async.cg 16B
// into a block-resident 144-row smem buffer (swizzled), waits warp-locally,
// then computes the round-5 fma-balanced inner loop from smem.
// ---------------------------------------------------------------------------
#define KB_ROWS_FLOATS (144 * 256)                        // 36864
#define KB_LOCC_FLOATS (256 * 16)                         // 4096
#define KB_SC_FLOATS   (K_ * 144)                         // 1728
#define KB_SMEM ((KB_ROWS_FLOATS + KB_LOCC_FLOATS + KB_SC_FLOATS) * 4)  // 170752

__global__ __launch_bounds__(288) void kB(const float* __restrict__ enc,
                                          const void* __restrict__ extIdxRaw) {
    extern __shared__ __align__(16) float smB[];
    float* rows_s = smB;                                   // [r][swizzled e], stride 256
    float* locC_t = smB + KB_ROWS_FLOATS;                  // [e][k^swz], stride 16
    float* scores = smB + KB_ROWS_FLOATS + KB_LOCC_FLOATS; // [k][144]

    const int blk = blockIdx.x;
    const int b = blk / W_, w = blk - b * W_;
    const int tid = threadIdx.x;
    const int wp = tid >> 5, lane = tid & 31;
    const int es = lane >> 2, ng = lane & 3;
    const int g = wp * 4 + ng;               // 0..35

    // extIdx dtype detection (int64 -> odd 32-bit words all zero)
    const int* p32 = (const int*)extIdxRaw;
    int orv = 0;
    #pragma unroll
    for (int q = 0; q < 16; q++) orv |= p32[2 * q + 1];
    const bool is64 = (orv == 0);
    const long long* p64 = (const long long*)extIdxRaw;

    // lane ell < 16 resolves the enc-row index for riw = ell of this warp
    int myRow = 0;
    if (lane < 16) {
        int r = wp * 16 + lane;
        if (r < 128) {
            size_t j = (size_t)(b * N_ + r) * W_ + w;
            int idx = is64 ? (int)p64[j] : p32[j];
            myRow = idx & (B_ * S_ - 1);
        } else if (r < 140) {
            myRow = b * S_ + (r - 128) + 1 + w;
        }
    }

    // warp-private coalesced staging of its 16 rows (16 KB), swizzled at 16B
    #pragma unroll
    for (int j = 0; j < 32; j++) {
        int t = j * 32 + lane;               // 0..1023
        int riw = t >> 6;                    // 0..15
        int e4  = t & 63;
        int srcRow = __shfl_sync(0xffffffffu, myRow, riw);
        int r = wp * 16 + riw;
        const float* src = enc + (size_t)srcRow * DENC + e4 * 4;
        float* dst = rows_s + r * 256 + ((e4 ^ ((r >> 2) & 7)) << 2);
        cp_async16(dst, src);
    }
    cp_commit();

    // block-shared locC tile: locC_t[e*16 + (k ^ (2*(e>>5)))]
    const float* lcg = g_locC + (size_t)blk * (K_ * 256);
    for (int q = tid; q < K_ * 256; q += 288) {
        int k = q >> 8, e = q & 255;
        locC_t[e * 16 + (k ^ ((e >> 5) << 1))] = lcg[q];
    }
    __syncthreads();        // locC_t visible

    cp_wait0();             // this warp's 16 rows landed
    __syncwarp();

    // thread rows: r_i = g*4 + i = 16wp + 4ng + i; swizzle key f = (4wp+ng)&7
    const int f = ((4 * wp + ng) & 7);
    const int r0 = g * 4;
    const float* rbase[4];
    #pragma unroll
    for (int i = 0; i < 4; i++) rbase[i] = rows_s + (r0 + i) * 256;

    ull acc[6][4];
    #pragma unroll
    for (int kp = 0; kp < 6; kp++)
        #pragma unroll
        for (int i = 0; i < 4; i++) acc[kp][i] = 0ull;

    const int sw = es << 1;
    #pragma unroll
    for (int ee4 = 0; ee4 < 8; ee4++) {
        const int e4 = es * 8 + ee4;
        float4 cur[4];
        #pragma unroll
        for (int i = 0; i < 4; i++)
            cur[i] = *(const float4*)(rbase[i] + ((e4 ^ f) << 2));
        #pragma unroll
        for (int d = 0; d < 4; d++) {
            const float* lcb = locC_t + (es * 32 + ee4 * 4 + d) * 16;
            ull lc[6];
            #pragma unroll
            for (int kp = 0; kp < 6; kp++) lc[kp] = *(const ull*)(lcb + ((2 * kp) ^ sw));
            #pragma unroll
            for (int i = 0; i < 4; i++) {
                float v = (d == 0) ? cur[i].x : (d == 1) ? cur[i].y : (d == 2) ? cur[i].z : cur[i].w;
                ull b2 = pack2(v, v);
                #pragma unroll
                for (int kp = 0; kp < 6; kp++)
                    acc[kp][i] = fma2(lc[kp], b2, acc[kp][i]);
            }
        }
    }

    // butterfly-reduce the 8 e-splits (lane bits 2,3,4)
    #pragma unroll
    for (int off = 4; off <= 16; off <<= 1)
        #pragma unroll
        for (int kp = 0; kp < 6; kp++)
            #pragma unroll
            for (int i = 0; i < 4; i++)
                acc[kp][i] = add2(acc[kp][i], __shfl_xor_sync(0xffffffffu, acc[kp][i], off));

    if (es == 0) {
        #pragma unroll
        for (int i = 0; i < 4; i++) {
            int r = g * 4 + i;
            if (r < 140) {
                #pragma unroll
                for (int kp = 0; kp < 6; kp++) {
                    float s0, s1; unpack2(s0, s1, acc[kp][i]);
                    scores[(2 * kp) * 144 + r]     = s0;
                    scores[(2 * kp + 1) * 144 + r] = s1;
                }
            }
        }
    }
    __syncthreads();

    // per-k logsumexp over [pos, 128 negs]; 9 warps cover 12 k
    for (int k = wp; k < K_; k += 9) {
        float v[4], mx = -1e30f;
        #pragma unroll
        for (int q = 0; q < 4; q++) {
            v[q] = scores[k * 144 + lane + q * 32] * INV_E;
            mx = fmaxf(mx, v[q]);
        }
        #pragma unroll
        for (int off = 16; off > 0; off >>= 1)
            mx = fmaxf(mx, __shfl_xor_sync(0xffffffffu, mx, off));
        const float pos = scores[k * 144 + 128 + k] * INV_E;
        const float mm = fmaxf(mx, pos);
        float se = 0.f;
        #pragma unroll
        for (int q = 0; q < 4; q++) se += __expf(v[q] - mm);
        #pragma unroll
        for (int off = 16; off > 0; off >>= 1)
            se += __shfl_xor_sync(0xffffffffu, se, off);
        if (lane == 0) {
            float lse = mm + __logf(se + __expf(pos - mm));
            g_part[(size_t)k * M_ + blk]        = lse - pos;
            g_part[(size_t)(12 + k) * M_ + blk] = (pos >= mx) ? 1.f : 0.f;
        }
    }
}

// ---------------------------------------------------------------------------
// kC: 24 blocks, each sums a contiguous 3712-float segment
// ---------------------------------------------------------------------------
__global__ __launch_bounds__(256) void kC(float* __restrict__ out) {
    __shared__ float red[8];
    const int j = blockIdx.x;
    const int tid = threadIdx.x, lane = tid & 31, wp = tid >> 5;
    const float* src = g_part + (size_t)j * M_;
    float s = 0.f;
    for (int i = tid; i < M_; i += 256) s += src[i];
    #pragma unroll
    for (int off = 16; off > 0; off >>= 1)
        s += __shfl_xor_sync(0xffffffffu, s, off);
    if (lane == 0) red[wp] = s;
    __syncthreads();
    if (tid < 8) {
        float v = red[tid];
        #pragma unroll
        for (int off = 4; off > 0; off >>= 1)
            v += __shfl_xor_sync(0xffu, v, off);
        if (tid == 0) out[j] = v * (1.0f / (float)M_);
    }
}

// ---------------------------------------------------------------------------
extern "C" void kernel_launch(void* const* d_in, const int* in_sizes, int n_in,
                              void* d_out, int out_size) {
    const float* cF  = (const float*)d_in[0];
    const float* enc = (const float*)d_in[1];
    const float* Wp  = (const float*)d_in[2];
    const void* eIdx = (const void*)d_in[3];
    float* out = (float*)d_out;

    static bool attrDone = false;
    if (!attrDone) {
        cudaFuncSetAttribute(kA, cudaFuncAttributeMaxDynamicSharedMemorySize, KA_SMEM);
        cudaFuncSetAttribute(kB, cudaFuncAttributeMaxDynamicSharedMemorySize, KB_SMEM);
        attrDone = true;
    }

    dim3 gT(8, 8, 12);
    kT<<<gT, 256>>>(Wp);
    dim3 gA(29, 2, 12);
    kA<<<gA, 256, KA_SMEM>>>(cF);
    kB<<<M_, 288, KB_SMEM>>>(enc, eIdx);
    kC<<<24, 256>>>(out);
}

// round 8
// speedup vs baseline: 1.5478x; 1.0691x over previous
#include <cuda_runtime.h>
#include <cuda_bf16.h>
#include <cstdint>

#define B_   32
#define S_   128
#define DAR  256
#define DENC 256
#define K_   12
#define N_   128
#define W_   116            // S - K
#define M_   (B_*W_)        // 3712
#define MT_  29
#define KSPL 1536           // 6 split-terms x 256
#define INV_E (1.0f/256.0f)

typedef unsigned long long ull;
typedef unsigned int u32;

// scratch (allocation-free rule: __device__ globals)
__device__ __align__(16) float g_locC[M_ * K_ * DENC];          // [m][k][e]
__device__ __align__(16) float g_part[24 * M_];                 // [j][site]
__device__ __align__(16) __nv_bfloat16 g_A2[M_ * KSPL];         // [m][1536]
__device__ __align__(16) __nv_bfloat16 g_B2[K_ * 256 * KSPL];   // [k*256+e][1536]

// ---------------- helpers ----------------
__device__ __forceinline__ ull pack2(float lo, float hi) {
    ull r; asm("mov.b64 %0, {%1, %2};" : "=l"(r) : "f"(lo), "f"(hi)); return r;
}
__device__ __forceinline__ void unpack2(float& lo, float& hi, ull v) {
    asm("mov.b64 {%0, %1}, %2;" : "=f"(lo), "=f"(hi) : "l"(v));
}
__device__ __forceinline__ ull fma2(ull a, ull b, ull c) {
    ull d; asm("fma.rn.f32x2 %0, %1, %2, %3;" : "=l"(d) : "l"(a), "l"(b), "l"(c)); return d;
}
__device__ __forceinline__ ull add2(ull a, ull b) {
    ull d; asm("add.rn.f32x2 %0, %1, %2;" : "=l"(d) : "l"(a), "l"(b)); return d;
}
__device__ __forceinline__ void cp_async16(void* dst, const void* src) {
    unsigned d = (unsigned)__cvta_generic_to_shared(dst);
    asm volatile("cp.async.cg.shared.global [%0], [%1], 16;" :: "r"(d), "l"(src));
}
__device__ __forceinline__ void cp_commit() { asm volatile("cp.async.commit_group;"); }
__device__ __forceinline__ void cp_wait0()  { asm volatile("cp.async.wait_group 0;"); }
__device__ __forceinline__ void cp_wait1()  { asm volatile("cp.async.wait_group 1;"); }
__device__ __forceinline__ u32 smem_u32(const void* p) {
    u32 a; asm("{ .reg .u64 t; cvta.to.shared.u64 t, %1; cvt.u32.u64 %0, t; }"
               : "=r"(a) : "l"(p));
    return a;
}
__device__ __forceinline__ void ldsm4(u32* r, u32 addr) {
    asm volatile("ldmatrix.sync.aligned.m8n8.x4.shared.b16 {%0,%1,%2,%3}, [%4];"
                 : "=r"(r[0]), "=r"(r[1]), "=r"(r[2]), "=r"(r[3]) : "r"(addr));
}
__device__ __forceinline__ void mma16816(float* c, const u32* a, const u32* b) {
    asm volatile(
        "mma.sync.aligned.m16n8k16.row.col.f32.bf16.bf16.f32 "
        "{%0,%1,%2,%3}, {%4,%5,%6,%7}, {%8,%9}, {%0,%1,%2,%3};"
        : "+f"(c[0]), "+f"(c[1]), "+f"(c[2]), "+f"(c[3])
        : "r"(a[0]), "r"(a[1]), "r"(a[2]), "r"(a[3]), "r"(b[0]), "r"(b[1]));
}

// ---------------------------------------------------------------------------
// kP: 3-way bf16 split -> A'/B' with 6-term K concatenation.
// A' term splits: {1,1,2,1,3,2}; B' term splits: {1,2,1,3,1,2} (0-indexed below)
// grid 848 x 256: CTA covers 8 rows; thread = (local row, 8-elem piece)
// ---------------------------------------------------------------------------
#define A_CTAS 464      // 3712/8
__global__ __launch_bounds__(256) void kP(const float* __restrict__ cF,
                                          const float* __restrict__ Wp) {
    const int blk = blockIdx.x;
    const int lrow = threadIdx.x >> 5;      // 0..7
    const int piece = threadIdx.x & 31;     // 8 elems each

    const float* src;
    __nv_bfloat16* dstRow;
    int ta[6];
    if (blk < A_CTAS) {
        int m = blk * 8 + lrow;
        int b = m / W_, w = m - b * W_;
        src = cF + (size_t)(b * S_ + w) * DAR;
        dstRow = g_A2 + (size_t)m * KSPL;
        ta[0] = 0; ta[1] = 0; ta[2] = 1; ta[3] = 0; ta[4] = 2; ta[5] = 1;
    } else {
        int row = (blk - A_CTAS) * 8 + lrow;        // k*256+e
        int k = row >> 8, e = row & 255;
        src = Wp + ((size_t)k * DENC + e) * DAR;
        dstRow = g_B2 + (size_t)row * KSPL;
        ta[0] = 0; ta[1] = 1; ta[2] = 0; ta[3] = 2; ta[4] = 0; ta[5] = 1;
    }

    float4 x0 = *(const float4*)(src + piece * 8);
    float4 x1 = *(const float4*)(src + piece * 8 + 4);
    float xs[8] = {x0.x, x0.y, x0.z, x0.w, x1.x, x1.y, x1.z, x1.w};

    u32 sp[3][4];      // 3 split levels, 8 bf16 each = 4 u32
    #pragma unroll
    for (int q = 0; q < 4; q++) {
        unsigned short h[3][2];
        #pragma unroll
        for (int d = 0; d < 2; d++) {
            float x = xs[2 * q + d];
            __nv_bfloat16 v1 = __float2bfloat16(x);
            float r = x - __bfloat162float(v1);
            __nv_bfloat16 v2 = __float2bfloat16(r);
            __nv_bfloat16 v3 = __float2bfloat16(r - __bfloat162float(v2));
            h[0][d] = __bfloat16_as_ushort(v1);
            h[1][d] = __bfloat16_as_ushort(v2);
            h[2][d] = __bfloat16_as_ushort(v3);
        }
        #pragma unroll
        for (int l = 0; l < 3; l++)
            sp[l][q] = ((u32)h[l][1] << 16) | h[l][0];
    }

    #pragma unroll
    for (int t = 0; t < 6; t++) {
        uint4 v = make_uint4(sp[ta[t]][0], sp[ta[t]][1], sp[ta[t]][2], sp[ta[t]][3]);
        *(uint4*)(dstRow + t * 256 + piece * 8) = v;
    }
}

// ---------------------------------------------------------------------------
// kA: bf16 mma.sync GEMM. grid (29 mt, 2 et, 12 k), 256 thr (8 warps).
// CTA tile M=128 x N=128 x K=1536; warp = (w&3)*32 m-rows x (w>>2)*64 e-cols.
// smem: double-buffered 64-K chunks; rows of 144B (72 bf16) for ldmatrix.
// ---------------------------------------------------------------------------
#define ROWB 144
#define STG_BYTES (128 * ROWB * 2)      // A(128 rows)+B(128 rows) = 36864
#define KA_SMEM (2 * STG_BYTES)         // 73728

__global__ __launch_bounds__(256) void kA() {
    extern __shared__ __align__(16) unsigned char smA[];
    const int tid = threadIdx.x, w = tid >> 5, lane = tid & 31;
    const int mt = blockIdx.x, et = blockIdx.y, k = blockIdx.z;
    const u32 sb = smem_u32(smA);

    const __nv_bfloat16* Ag = g_A2 + (size_t)(mt * 128) * KSPL;
    const __nv_bfloat16* Bg = g_B2 + (size_t)(k * 256 + et * 128) * KSPL;

    // per-thread staging coords: 8 segs (4 A, 4 B), seg = tid + j*256
    int sRow[8]; int sPiece[8];
    #pragma unroll
    for (int j = 0; j < 8; j++) {
        int seg = tid + (j & 3) * 256;
        sRow[j] = seg >> 3; sPiece[j] = seg & 7;
    }

    float acc[2][8][4];
    #pragma unroll
    for (int i = 0; i < 2; i++)
        #pragma unroll
        for (int n = 0; n < 8; n++)
            #pragma unroll
            for (int q = 0; q < 4; q++) acc[i][n][q] = 0.f;

    // stage issuer
    auto issue = [&](int c, int buf) {
        unsigned char* base = smA + buf * STG_BYTES;
        #pragma unroll
        for (int j = 0; j < 4; j++)
            cp_async16(base + sRow[j] * ROWB + sPiece[j] * 16,
                       Ag + (size_t)sRow[j] * KSPL + c * 64 + sPiece[j] * 8);
        #pragma unroll
        for (int j = 4; j < 8; j++)
            cp_async16(base + 128 * ROWB + sRow[j] * ROWB + sPiece[j] * 16,
                       Bg + (size_t)sRow[j] * KSPL + c * 64 + sPiece[j] * 8);
        cp_commit();
    };

    issue(0, 0);

    const u32 aRowSel = (lane & 15);
    const u32 aHalf   = (lane >> 4);
    const u32 bRowSel = (lane & 7) + ((lane >> 4) << 3);
    const u32 bHalf   = (lane >> 3) & 1;

    for (int c = 0; c < 24; c++) {
        if (c < 23) issue(c + 1, (c + 1) & 1);
        if (c < 23) cp_wait1(); else cp_wait0();
        __syncthreads();

        const u32 Abase = sb + (c & 1) * STG_BYTES;
        const u32 Bbase = Abase + 128 * ROWB;

        #pragma unroll
        for (int ks = 0; ks < 4; ks++) {
            u32 afr[2][4];
            #pragma unroll
            for (int mtile = 0; mtile < 2; mtile++) {
                u32 addr = Abase + ((w & 3) * 32 + mtile * 16 + aRowSel) * ROWB
                         + aHalf * 16 + ks * 32;
                ldsm4(afr[mtile], addr);
            }
            u32 bfr[4][4];
            #pragma unroll
            for (int nt2 = 0; nt2 < 4; nt2++) {
                u32 addr = Bbase + ((w >> 2) * 64 + nt2 * 16 + bRowSel) * ROWB
                         + bHalf * 16 + ks * 32;
                ldsm4(bfr[nt2], addr);
            }
            #pragma unroll
            for (int mtile = 0; mtile < 2; mtile++)
                #pragma unroll
                for (int nt = 0; nt < 8; nt++)
                    mma16816(acc[mtile][nt], afr[mtile], &bfr[nt >> 1][(nt & 1) * 2]);
        }
        __syncthreads();
    }

    // epilogue: float2 stores to g_locC[m][k][e]
    const int mW = mt * 128 + (w & 3) * 32 + (lane >> 2);
    const int eW = et * 128 + (w >> 2) * 64 + (lane & 3) * 2;
    #pragma unroll
    for (int mtile = 0; mtile < 2; mtile++) {
        #pragma unroll
        for (int nt = 0; nt < 8; nt++) {
            int m0 = mW + mtile * 16;
            int e0 = eW + nt * 8;
            float* d0 = g_locC + ((size_t)m0 * K_ + k) * 256 + e0;
            float* d1 = g_locC + ((size_t)(m0 + 8) * K_ + k) * 256 + e0;
            *(float2*)d0 = make_float2(acc[mtile][nt][0], acc[mtile][nt][1]);
            *(float2*)d1 = make_float2(acc[mtile][nt][2], acc[mtile][nt][3]);
        }
    }
}

// ---------------------------------------------------------------------------
// kB: per-site scores + logsumexp (round-6 version, unchanged)
// ---------------------------------------------------------------------------
#define KB_ROWS_FLOATS (144 * 256)
#define KB_LOCC_FLOATS (256 * 16)
#define KB_SC_FLOATS   (K_ * 144)
#define KB_SMEM ((KB_ROWS_FLOATS + KB_LOCC_FLOATS + KB_SC_FLOATS) * 4)

__global__ __launch_bounds__(288) void kB(const float* __restrict__ enc,
                                          const void* __restrict__ extIdxRaw) {
    extern __shared__ __align__(16) float smB[];
    float* rows_s = smB;
    float* locC_t = smB + KB_ROWS_FLOATS;
    float* scores = smB + KB_ROWS_FLOATS + KB_LOCC_FLOATS;

    const int blk = blockIdx.x;
    const int b = blk / W_, w = blk - b * W_;
    const int tid = threadIdx.x;
    const int wp = tid >> 5, lane = tid & 31;
    const int es = lane >> 2, ng = lane & 3;
    const int g = wp * 4 + ng;

    const int* p32 = (const int*)extIdxRaw;
    int orv = 0;
    #pragma unroll
    for (int q = 0; q < 16; q++) orv |= p32[2 * q + 1];
    const bool is64 = (orv == 0);
    const long long* p64 = (const long long*)extIdxRaw;

    int myRow = 0;
    if (lane < 16) {
        int r = wp * 16 + lane;
        if (r < 128) {
            size_t j = (size_t)(b * N_ + r) * W_ + w;
            int idx = is64 ? (int)p64[j] : p32[j];
            myRow = idx & (B_ * S_ - 1);
        } else if (r < 140) {
            myRow = b * S_ + (r - 128) + 1 + w;
        }
    }

    #pragma unroll
    for (int j = 0; j < 32; j++) {
        int t = j * 32 + lane;
        int riw = t >> 6, e4 = t & 63;
        int srcRow = __shfl_sync(0xffffffffu, myRow, riw);
        int r = wp * 16 + riw;
        cp_async16(rows_s + r * 256 + ((e4 ^ ((r >> 2) & 7)) << 2),
                   enc + (size_t)srcRow * DENC + e4 * 4);
    }
    cp_commit();

    const float* lcg = g_locC + (size_t)blk * (K_ * 256);
    for (int q = tid; q < K_ * 256; q += 288) {
        int k = q >> 8, e = q & 255;
        locC_t[e * 16 + (k ^ ((e >> 5) << 1))] = lcg[q];
    }
    __syncthreads();
    cp_wait0();
    __syncwarp();

    const int f = ((4 * wp + ng) & 7);
    const int r0 = g * 4;
    const float* rbase[4];
    #pragma unroll
    for (int i = 0; i < 4; i++) rbase[i] = rows_s + (r0 + i) * 256;

    ull acc[6][4];
    #pragma unroll
    for (int kp = 0; kp < 6; kp++)
        #pragma unroll
        for (int i = 0; i < 4; i++) acc[kp][i] = 0ull;

    const int sw = es << 1;
    #pragma unroll
    for (int ee4 = 0; ee4 < 8; ee4++) {
        const int e4 = es * 8 + ee4;
        float4 cur[4];
        #pragma unroll
        for (int i = 0; i < 4; i++)
            cur[i] = *(const float4*)(rbase[i] + ((e4 ^ f) << 2));
        #pragma unroll
        for (int d = 0; d < 4; d++) {
            const float* lcb = locC_t + (es * 32 + ee4 * 4 + d) * 16;
            ull lc[6];
            #pragma unroll
            for (int kp = 0; kp < 6; kp++) lc[kp] = *(const ull*)(lcb + ((2 * kp) ^ sw));
            #pragma unroll
            for (int i = 0; i < 4; i++) {
                float v = (d == 0) ? cur[i].x : (d == 1) ? cur[i].y : (d == 2) ? cur[i].z : cur[i].w;
                ull b2 = pack2(v, v);
                #pragma unroll
                for (int kp = 0; kp < 6; kp++)
                    acc[kp][i] = fma2(lc[kp], b2, acc[kp][i]);
            }
        }
    }

    #pragma unroll
    for (int off = 4; off <= 16; off <<= 1)
        #pragma unroll
        for (int kp = 0; kp < 6; kp++)
            #pragma unroll
            for (int i = 0; i < 4; i++)
                acc[kp][i] = add2(acc[kp][i], __shfl_xor_sync(0xffffffffu, acc[kp][i], off));

    if (es == 0) {
        #pragma unroll
        for (int i = 0; i < 4; i++) {
            int r = g * 4 + i;
            if (r < 140) {
                #pragma unroll
                for (int kp = 0; kp < 6; kp++) {
                    float s0, s1; unpack2(s0, s1, acc[kp][i]);
                    scores[(2 * kp) * 144 + r]     = s0;
                    scores[(2 * kp + 1) * 144 + r] = s1;
                }
            }
        }
    }
    __syncthreads();

    for (int k = wp; k < K_; k += 9) {
        float v[4], mx = -1e30f;
        #pragma unroll
        for (int q = 0; q < 4; q++) {
            v[q] = scores[k * 144 + lane + q * 32] * INV_E;
            mx = fmaxf(mx, v[q]);
        }
        #pragma unroll
        for (int off = 16; off > 0; off >>= 1)
            mx = fmaxf(mx, __shfl_xor_sync(0xffffffffu, mx, off));
        const float pos = scores[k * 144 + 128 + k] * INV_E;
        const float mm = fmaxf(mx, pos);
        float se = 0.f;
        #pragma unroll
        for (int q = 0; q < 4; q++) se += __expf(v[q] - mm);
        #pragma unroll
        for (int off = 16; off > 0; off >>= 1)
            se += __shfl_xor_sync(0xffffffffu, se, off);
        if (lane == 0) {
            float lse = mm + __logf(se + __expf(pos - mm));
            g_part[(size_t)k * M_ + blk]        = lse - pos;
            g_part[(size_t)(12 + k) * M_ + blk] = (pos >= mx) ? 1.f : 0.f;
        }
    }
}

// ---------------------------------------------------------------------------
// kC: 24 blocks, each sums a contiguous 3712-float segment
// ---------------------------------------------------------------------------
__global__ __launch_bounds__(256) void kC(float* __restrict__ out) {
    __shared__ float red[8];
    const int j = blockIdx.x;
    const int tid = threadIdx.x, lane = tid & 31, wp = tid >> 5;
    const float* src = g_part + (size_t)j * M_;
    float s = 0.f;
    for (int i = tid; i < M_; i += 256) s += src[i];
    #pragma unroll
    for (int off = 16; off > 0; off >>= 1)
        s += __shfl_xor_sync(0xffffffffu, s, off);
    if (lane == 0) red[wp] = s;
    __syncthreads();
    if (tid < 8) {
        float v = red[tid];
        #pragma unroll
        for (int off = 4; off > 0; off >>= 1)
            v += __shfl_xor_sync(0xffu, v, off);
        if (tid == 0) out[j] = v * (1.0f / (float)M_);
    }
}

// ---------------------------------------------------------------------------
extern "C" void kernel_launch(void* const* d_in, const int* in_sizes, int n_in,
                              void* d_out, int out_size) {
    const float* cF  = (const float*)d_in[0];
    const float* enc = (const float*)d_in[1];
    const float* Wp  = (const float*)d_in[2];
    const void* eIdx = (const void*)d_in[3];
    float* out = (float*)d_out;

    cudaFuncSetAttribute(kA, cudaFuncAttributeMaxDynamicSharedMemorySize, KA_SMEM);
    cudaFuncSetAttribute(kB, cudaFuncAttributeMaxDynamicSharedMemorySize, KB_SMEM);

    kP<<<A_CTAS + 384, 256>>>(cF, Wp);
    dim3 gA(MT_, 2, K_);
    kA<<<gA, 256, KA_SMEM>>>();
    kB<<<M_, 288, KB_SMEM>>>(enc, eIdx);
    kC<<<24, 256>>>(out);
}

// round 9
// speedup vs baseline: 1.8574x; 1.2000x over previous
#include <cuda_runtime.h>
#include <cuda_bf16.h>
#include <cstdint>

#define B_   32
#define S_   128
#define DAR  256
#define DENC 256
#define K_   12
#define N_   128
#define W_   116            // S - K
#define M_   (B_*W_)        // 3712
#define MT_  29
#define KSPL 1536           // 6 split-terms x 256
#define INV_E (1.0f/256.0f)

typedef unsigned long long ull;
typedef unsigned int u32;

// scratch (allocation-free rule: __device__ globals)
__device__ __align__(16) float g_locC[M_ * K_ * DENC];          // [m][k][e]
__device__ __align__(16) float g_part[24 * M_];                 // [j][site]
__device__ __align__(16) __nv_bfloat16 g_A2[M_ * KSPL];         // [m][1536]
__device__ __align__(16) __nv_bfloat16 g_B2[K_ * 256 * KSPL];   // [k*256+e][1536]

// ---------------- helpers ----------------
__device__ __forceinline__ ull pack2(float lo, float hi) {
    ull r; asm("mov.b64 %0, {%1, %2};" : "=l"(r) : "f"(lo), "f"(hi)); return r;
}
__device__ __forceinline__ void unpack2(float& lo, float& hi, ull v) {
    asm("mov.b64 {%0, %1}, %2;" : "=f"(lo), "=f"(hi) : "l"(v));
}
__device__ __forceinline__ ull fma2(ull a, ull b, ull c) {
    ull d; asm("fma.rn.f32x2 %0, %1, %2, %3;" : "=l"(d) : "l"(a), "l"(b), "l"(c)); return d;
}
__device__ __forceinline__ ull add2(ull a, ull b) {
    ull d; asm("add.rn.f32x2 %0, %1, %2;" : "=l"(d) : "l"(a), "l"(b)); return d;
}
__device__ __forceinline__ void cp_async16(void* dst, const void* src) {
    unsigned d = (unsigned)__cvta_generic_to_shared(dst);
    asm volatile("cp.async.cg.shared.global [%0], [%1], 16;" :: "r"(d), "l"(src));
}
__device__ __forceinline__ void cp_commit() { asm volatile("cp.async.commit_group;"); }
__device__ __forceinline__ void cp_wait0()  { asm volatile("cp.async.wait_group 0;"); }
__device__ __forceinline__ void cp_wait1()  { asm volatile("cp.async.wait_group 1;"); }
__device__ __forceinline__ void cp_wait2()  { asm volatile("cp.async.wait_group 2;"); }
__device__ __forceinline__ u32 smem_u32(const void* p) {
    u32 a; asm("{ .reg .u64 t; cvta.to.shared.u64 t, %1; cvt.u32.u64 %0, t; }"
               : "=r"(a) : "l"(p));
    return a;
}
__device__ __forceinline__ void ldsm4(u32* r, u32 addr) {
    asm volatile("ldmatrix.sync.aligned.m8n8.x4.shared.b16 {%0,%1,%2,%3}, [%4];"
                 : "=r"(r[0]), "=r"(r[1]), "=r"(r[2]), "=r"(r[3]) : "r"(addr));
}
__device__ __forceinline__ void mma16816(float* c, const u32* a, const u32* b) {
    asm volatile(
        "mma.sync.aligned.m16n8k16.row.col.f32.bf16.bf16.f32 "
        "{%0,%1,%2,%3}, {%4,%5,%6,%7}, {%8,%9}, {%0,%1,%2,%3};"
        : "+f"(c[0]), "+f"(c[1]), "+f"(c[2]), "+f"(c[3])
        : "r"(a[0]), "r"(a[1]), "r"(a[2]), "r"(a[3]), "r"(b[0]), "r"(b[1]));
}

// ---------------------------------------------------------------------------
// kP: 3-way bf16 split -> A'/B' with 6-term K concatenation (unchanged)
// ---------------------------------------------------------------------------
#define A_CTAS 464      // 3712/8
__global__ __launch_bounds__(256) void kP(const float* __restrict__ cF,
                                          const float* __restrict__ Wp) {
    const int blk = blockIdx.x;
    const int lrow = threadIdx.x >> 5;
    const int piece = threadIdx.x & 31;

    const float* src;
    __nv_bfloat16* dstRow;
    int ta[6];
    if (blk < A_CTAS) {
        int m = blk * 8 + lrow;
        int b = m / W_, w = m - b * W_;
        src = cF + (size_t)(b * S_ + w) * DAR;
        dstRow = g_A2 + (size_t)m * KSPL;
        ta[0] = 0; ta[1] = 0; ta[2] = 1; ta[3] = 0; ta[4] = 2; ta[5] = 1;
    } else {
        int row = (blk - A_CTAS) * 8 + lrow;
        int k = row >> 8, e = row & 255;
        src = Wp + ((size_t)k * DENC + e) * DAR;
        dstRow = g_B2 + (size_t)row * KSPL;
        ta[0] = 0; ta[1] = 1; ta[2] = 0; ta[3] = 2; ta[4] = 0; ta[5] = 1;
    }

    float4 x0 = *(const float4*)(src + piece * 8);
    float4 x1 = *(const float4*)(src + piece * 8 + 4);
    float xs[8] = {x0.x, x0.y, x0.z, x0.w, x1.x, x1.y, x1.z, x1.w};

    u32 sp[3][4];
    #pragma unroll
    for (int q = 0; q < 4; q++) {
        unsigned short h[3][2];
        #pragma unroll
        for (int d = 0; d < 2; d++) {
            float x = xs[2 * q + d];
            __nv_bfloat16 v1 = __float2bfloat16(x);
            float r = x - __bfloat162float(v1);
            __nv_bfloat16 v2 = __float2bfloat16(r);
            __nv_bfloat16 v3 = __float2bfloat16(r - __bfloat162float(v2));
            h[0][d] = __bfloat16_as_ushort(v1);
            h[1][d] = __bfloat16_as_ushort(v2);
            h[2][d] = __bfloat16_as_ushort(v3);
        }
        #pragma unroll
        for (int l = 0; l < 3; l++)
            sp[l][q] = ((u32)h[l][1] << 16) | h[l][0];
    }

    #pragma unroll
    for (int t = 0; t < 6; t++) {
        uint4 v = make_uint4(sp[ta[t]][0], sp[ta[t]][1], sp[ta[t]][2], sp[ta[t]][3]);
        *(uint4*)(dstRow + t * 256 + piece * 8) = v;
    }
}

// ---------------------------------------------------------------------------
// kA: bf16 mma.sync GEMM, 3-stage cp.async pipeline, 2 CTAs/SM.
// grid (29, 2, 12), 256 thr. CTA tile M=128 x N=128 x K=1536.
// ---------------------------------------------------------------------------
#define ROWB 144
#define STG_BYTES (128 * ROWB * 2)      // 36864
#define KA_SMEM (3 * STG_BYTES)         // 110592

__global__ __launch_bounds__(256, 2) void kA() {
    extern __shared__ __align__(16) unsigned char smA[];
    const int tid = threadIdx.x, w = tid >> 5, lane = tid & 31;
    const int mt = blockIdx.x, et = blockIdx.y, k = blockIdx.z;
    const u32 sb = smem_u32(smA);

    const __nv_bfloat16* Ag = g_A2 + (size_t)(mt * 128) * KSPL;
    const __nv_bfloat16* Bg = g_B2 + (size_t)(k * 256 + et * 128) * KSPL;

    float acc[2][8][4];
    #pragma unroll
    for (int i = 0; i < 2; i++)
        #pragma unroll
        for (int n = 0; n < 8; n++)
            #pragma unroll
            for (int q = 0; q < 4; q++) acc[i][n][q] = 0.f;

    auto issue = [&](int c, int buf) {
        unsigned char* base = smA + buf * STG_BYTES;
        #pragma unroll
        for (int j = 0; j < 4; j++) {
            int seg = tid + j * 256;
            int row = seg >> 3, pc = seg & 7;
            cp_async16(base + row * ROWB + pc * 16,
                       Ag + (size_t)row * KSPL + c * 64 + pc * 8);
        }
        #pragma unroll
        for (int j = 0; j < 4; j++) {
            int seg = tid + j * 256;
            int row = seg >> 3, pc = seg & 7;
            cp_async16(base + 128 * ROWB + row * ROWB + pc * 16,
                       Bg + (size_t)row * KSPL + c * 64 + pc * 8);
        }
        cp_commit();
    };

    issue(0, 0); issue(1, 1); issue(2, 2);

    const u32 aRowSel = (lane & 15);
    const u32 aHalf   = (lane >> 4);
    const u32 bRowSel = (lane & 7) + ((lane >> 4) << 3);
    const u32 bHalf   = (lane >> 3) & 1;

    for (int c = 0; c < 24; c++) {
        if (c <= 21) cp_wait2(); else if (c == 22) cp_wait1(); else cp_wait0();
        __syncthreads();

        const u32 Abase = sb + (c % 3) * STG_BYTES;
        const u32 Bbase = Abase + 128 * ROWB;

        #pragma unroll
        for (int ks = 0; ks < 4; ks++) {
            u32 afr[2][4];
            #pragma unroll
            for (int mtile = 0; mtile < 2; mtile++) {
                u32 addr = Abase + ((w & 3) * 32 + mtile * 16 + aRowSel) * ROWB
                         + aHalf * 16 + ks * 32;
                ldsm4(afr[mtile], addr);
            }
            u32 bfr[4][4];
            #pragma unroll
            for (int nt2 = 0; nt2 < 4; nt2++) {
                u32 addr = Bbase + ((w >> 2) * 64 + nt2 * 16 + bRowSel) * ROWB
                         + bHalf * 16 + ks * 32;
                ldsm4(bfr[nt2], addr);
            }
            #pragma unroll
            for (int mtile = 0; mtile < 2; mtile++)
                #pragma unroll
                for (int nt = 0; nt < 8; nt++)
                    mma16816(acc[mtile][nt], afr[mtile], &bfr[nt >> 1][(nt & 1) * 2]);
        }
        __syncthreads();
        if (c < 21) issue(c + 3, (c + 3) % 3);
    }

    const int mW = mt * 128 + (w & 3) * 32 + (lane >> 2);
    const int eW = et * 128 + (w >> 2) * 64 + (lane & 3) * 2;
    #pragma unroll
    for (int mtile = 0; mtile < 2; mtile++) {
        #pragma unroll
        for (int nt = 0; nt < 8; nt++) {
            int m0 = mW + mtile * 16;
            int e0 = eW + nt * 8;
            float* d0 = g_locC + ((size_t)m0 * K_ + k) * 256 + e0;
            float* d1 = g_locC + ((size_t)(m0 + 8) * K_ + k) * 256 + e0;
            *(float2*)d0 = make_float2(acc[mtile][nt][0], acc[mtile][nt][1]);
            *(float2*)d1 = make_float2(acc[mtile][nt][2], acc[mtile][nt][3]);
        }
    }
}

// ---------------------------------------------------------------------------
// kB v4: two 72-row passes, 2 CTAs/SM, conflict-free stride-260 rows.
// 3712 CTAs x 288 thr. Warp wp owns local rows [8wp, 8wp+8) each pass.
// Thread (wp, es=lane>>2, ng=lane&3): rows 8wp+2ng+{0,1}, e-slice es*32.
// Row swizzle: col = e4 ^ ((e4>>3)&1); bank group = (row + col) mod 8.
// ---------------------------------------------------------------------------
#define RSTR 260
#define KB_ROWS_FLOATS (72 * RSTR)      // 18720
#define KB_LOCC_FLOATS (256 * 16)       // 4096
#define KB_SC_FLOATS   (K_ * 144)       // 1728
#define KB_SMEM ((KB_ROWS_FLOATS + KB_LOCC_FLOATS + KB_SC_FLOATS) * 4)  // 98176

__global__ __launch_bounds__(288, 2) void kB(const float* __restrict__ enc,
                                             const void* __restrict__ extIdxRaw) {
    extern __shared__ __align__(16) float smB[];
    float* rows_s = smB;                                   // [72][RSTR]
    float* locC_t = smB + KB_ROWS_FLOATS;                  // [e][k^swz] stride 16
    float* scores = smB + KB_ROWS_FLOATS + KB_LOCC_FLOATS; // [k][144]

    const int blk = blockIdx.x;
    const int b = blk / W_, w = blk - b * W_;
    const int tid = threadIdx.x;
    const int wp = tid >> 5, lane = tid & 31;
    const int es = lane >> 2, ng = lane & 3;

    // extIdx dtype detection (int64 -> odd 32-bit words all zero)
    const int* p32 = (const int*)extIdxRaw;
    int orv = 0;
    #pragma unroll
    for (int q = 0; q < 16; q++) orv |= p32[2 * q + 1];
    const bool is64 = (orv == 0);
    const long long* p64 = (const long long*)extIdxRaw;

    // lane<16 resolves enc-row for global row (lane>>3)*72 + wp*8 + (lane&7)
    int myRow = 0;
    if (lane < 16) {
        int r = (lane >> 3) * 72 + wp * 8 + (lane & 7);
        if (r < 128) {
            size_t j = (size_t)(b * N_ + r) * W_ + w;
            int idx = is64 ? (int)p64[j] : p32[j];
            myRow = idx & (B_ * S_ - 1);
        } else if (r < 140) {
            myRow = b * S_ + (r - 128) + 1 + w;
        }
    }

    // issue pass-0 staging (8 rows per warp, 16 iters)
    #pragma unroll
    for (int j = 0; j < 16; j++) {
        int t = j * 32 + lane;                // 0..511
        int riw = t >> 6, e4 = t & 63;
        int srcRow = __shfl_sync(0xffffffffu, myRow, riw);
        int rr = wp * 8 + riw;
        int col = e4 ^ ((e4 >> 3) & 1);
        cp_async16(rows_s + rr * RSTR + col * 4,
                   enc + (size_t)srcRow * DENC + e4 * 4);
    }
    cp_commit();

    // locC tile via plain LDG/STS: locC_t[e*16 + (k ^ 2*(e>>5))]
    const float* lcg = g_locC + (size_t)blk * (K_ * 256);
    for (int q = tid; q < K_ * 256; q += 288) {
        int k = q >> 8, e = q & 255;
        locC_t[e * 16 + (k ^ ((e >> 5) << 1))] = lcg[q];
    }
    __syncthreads();    // locC visible to all warps

    const int sw = es << 1;
    const int rr0 = wp * 8 + ng * 2;          // thread's local rows rr0, rr0+1

    #pragma unroll
    for (int pass = 0; pass < 2; pass++) {
        cp_wait0();
        __syncwarp();

        ull acc[6][2];
        #pragma unroll
        for (int kp = 0; kp < 6; kp++) { acc[kp][0] = 0ull; acc[kp][1] = 0ull; }

        #pragma unroll
        for (int ee4 = 0; ee4 < 8; ee4++) {
            const int e4 = es * 8 + ee4;
            const int col = e4 ^ (es & 1);
            float4 cur[2];
            cur[0] = *(const float4*)(rows_s + rr0 * RSTR + col * 4);
            cur[1] = *(const float4*)(rows_s + (rr0 + 1) * RSTR + col * 4);
            #pragma unroll
            for (int d = 0; d < 4; d++) {
                const float* lcb = locC_t + (es * 32 + ee4 * 4 + d) * 16;
                ull lc[6];
                #pragma unroll
                for (int kp = 0; kp < 6; kp++) lc[kp] = *(const ull*)(lcb + ((2 * kp) ^ sw));
                #pragma unroll
                for (int i = 0; i < 2; i++) {
                    float v = (d == 0) ? cur[i].x : (d == 1) ? cur[i].y
                            : (d == 2) ? cur[i].z : cur[i].w;
                    ull b2 = pack2(v, v);
                    #pragma unroll
                    for (int kp = 0; kp < 6; kp++)
                        acc[kp][i] = fma2(lc[kp], b2, acc[kp][i]);
                }
            }
        }

        // butterfly-reduce the 8 e-splits (lane bits 2,3,4)
        #pragma unroll
        for (int off = 4; off <= 16; off <<= 1)
            #pragma unroll
            for (int kp = 0; kp < 6; kp++)
                #pragma unroll
                for (int i = 0; i < 2; i++)
                    acc[kp][i] = add2(acc[kp][i], __shfl_xor_sync(0xffffffffu, acc[kp][i], off));

        if (es == 0) {
            #pragma unroll
            for (int i = 0; i < 2; i++) {
                int r = pass * 72 + rr0 + i;
                if (r < 140) {
                    #pragma unroll
                    for (int kp = 0; kp < 6; kp++) {
                        float s0, s1; unpack2(s0, s1, acc[kp][i]);
                        scores[(2 * kp) * 144 + r]     = s0;
                        scores[(2 * kp + 1) * 144 + r] = s1;
                    }
                }
            }
        }

        // issue pass-1 staging into the same warp-local rows
        if (pass == 0) {
            #pragma unroll
            for (int j = 0; j < 16; j++) {
                int t = j * 32 + lane;
                int riw = t >> 6, e4 = t & 63;
                int srcRow = __shfl_sync(0xffffffffu, myRow, 8 + riw);
                int rr = wp * 8 + riw;
                int col = e4 ^ ((e4 >> 3) & 1);
                cp_async16(rows_s + rr * RSTR + col * 4,
                           enc + (size_t)srcRow * DENC + e4 * 4);
            }
            cp_commit();
        }
    }
    __syncthreads();

    // per-k logsumexp over [pos, 128 negs]; 9 warps cover 12 k
    for (int k = wp; k < K_; k += 9) {
        float v[4], mx = -1e30f;
        #pragma unroll
        for (int q = 0; q < 4; q++) {
            v[q] = scores[k * 144 + lane + q * 32] * INV_E;
            mx = fmaxf(mx, v[q]);
        }
        #pragma unroll
        for (int off = 16; off > 0; off >>= 1)
            mx = fmaxf(mx, __shfl_xor_sync(0xffffffffu, mx, off));
        const float pos = scores[k * 144 + 128 + k] * INV_E;
        const float mm = fmaxf(mx, pos);
        float se = 0.f;
        #pragma unroll
        for (int q = 0; q < 4; q++) se += __expf(v[q] - mm);
        #pragma unroll
        for (int off = 16; off > 0; off >>= 1)
            se += __shfl_xor_sync(0xffffffffu, se, off);
        if (lane == 0) {
            float lse = mm + __logf(se + __expf(pos - mm));
            g_part[(size_t)k * M_ + blk]        = lse - pos;
            g_part[(size_t)(12 + k) * M_ + blk] = (pos >= mx) ? 1.f : 0.f;
        }
    }
}

// ---------------------------------------------------------------------------
// kC: 24 blocks, each sums a contiguous 3712-float segment
// ---------------------------------------------------------------------------
__global__ __launch_bounds__(256) void kC(float* __restrict__ out) {
    __shared__ float red[8];
    const int j = blockIdx.x;
    const int tid = threadIdx.x, lane = tid & 31, wp = tid >> 5;
    const float* src = g_part + (size_t)j * M_;
    float s = 0.f;
    for (int i = tid; i < M_; i += 256) s += src[i];
    #pragma unroll
    for (int off = 16; off > 0; off >>= 1)
        s += __shfl_xor_sync(0xffffffffu, s, off);
    if (lane == 0) red[wp] = s;
    __syncthreads();
    if (tid < 8) {
        float v = red[tid];
        #pragma unroll
        for (int off = 4; off > 0; off >>= 1)
            v += __shfl_xor_sync(0xffu, v, off);
        if (tid == 0) out[j] = v * (1.0f / (float)M_);
    }
}

// ---------------------------------------------------------------------------
extern "C" void kernel_launch(void* const* d_in, const int* in_sizes, int n_in,
                              void* d_out, int out_size) {
    const float* cF  = (const float*)d_in[0];
    const float* enc = (const float*)d_in[1];
    const float* Wp  = (const float*)d_in[2];
    const void* eIdx = (const void*)d_in[3];
    float* out = (float*)d_out;

    cudaFuncSetAttribute(kA, cudaFuncAttributeMaxDynamicSharedMemorySize, KA_SMEM);
    cudaFuncSetAttribute(kB, cudaFuncAttributeMaxDynamicSharedMemorySize, KB_SMEM);

    kP<<<A_CTAS + 384, 256>>>(cF, Wp);
    dim3 gA(MT_, 2, K_);
    kA<<<gA, 256, KA_SMEM>>>();
    kB<<<M_, 288, KB_SMEM>>>(enc, eIdx);
    kC<<<24, 256>>>(out);
}